// round 8
// baseline (speedup 1.0000x reference)
#include <cuda_runtime.h>
#include <cuda_bf16.h>
#include <math.h>
#include <cstdint>

// ---------------------------------------------------------------------------
// Problem constants (fixed by setup_inputs)
// ---------------------------------------------------------------------------
namespace {
constexpr int kBN   = 16;
constexpr int kT    = 12;
constexpr int kCH   = 128;
constexpr int kH    = 24, kW = 24;
constexpr int kHW   = 576;
constexpr int kTm1  = 11;
constexpr int kTp   = 9;
constexpr int kNB   = 144;    // kBN * kTp
constexpr int kVCH  = 146;
constexpr int kSSTA = 32;
constexpr int kCP   = 114;
constexpr int kNAtt = 176;    // kBN * kTm1
constexpr float kScale = 0.0883883476483184f;  // 128^-0.5
constexpr int kLds  = 40;     // smem row stride in halves (80 B, conflict-free)
}

// ---------------------------------------------------------------------------
// Low-level helpers
// ---------------------------------------------------------------------------
__device__ __forceinline__ unsigned long long pack2(float lo, float hi) {
    unsigned long long r;
    asm("mov.b64 %0, {%1, %2};" : "=l"(r) : "f"(lo), "f"(hi));
    return r;
}
__device__ __forceinline__ unsigned long long dup2(float v) { return pack2(v, v); }
__device__ __forceinline__ void ffma2(unsigned long long& d, unsigned long long a,
                                      unsigned long long b) {
    asm("fma.rn.f32x2 %0, %1, %2, %3;" : "=l"(d) : "l"(a), "l"(b), "l"(d));
}
__device__ __forceinline__ void unpack2(unsigned long long v, float& lo, float& hi) {
    asm("mov.b64 {%0, %1}, %2;" : "=f"(lo), "=f"(hi) : "l"(v));
}

__device__ __forceinline__ void mma16816(float* c, const uint32_t* a, const uint32_t* b) {
    asm volatile(
        "mma.sync.aligned.m16n8k16.row.col.f32.bf16.bf16.f32 "
        "{%0,%1,%2,%3}, {%4,%5,%6,%7}, {%8,%9}, {%0,%1,%2,%3};"
        : "+f"(c[0]), "+f"(c[1]), "+f"(c[2]), "+f"(c[3])
        : "r"(a[0]), "r"(a[1]), "r"(a[2]), "r"(a[3]), "r"(b[0]), "r"(b[1]));
}

__device__ __forceinline__ uint32_t smem_u32p(const void* p) {
    uint32_t a;
    asm("{ .reg .u64 t; cvta.to.shared.u64 t, %1; cvt.u32.u64 %0, t; }"
        : "=r"(a) : "l"(p));
    return a;
}
__device__ __forceinline__ void ldm_x4(uint32_t* r, uint32_t saddr) {
    asm volatile("ldmatrix.sync.aligned.m8n8.x4.shared.b16 {%0,%1,%2,%3}, [%4];"
                 : "=r"(r[0]), "=r"(r[1]), "=r"(r[2]), "=r"(r[3]) : "r"(saddr));
}
__device__ __forceinline__ void cpasync16(void* sdst, const void* gsrc) {
    asm volatile("cp.async.ca.shared.global [%0], [%1], 16;"
                 :: "r"(smem_u32p(sdst)), "l"(gsrc));
}
__device__ __forceinline__ void cp_commit() {
    asm volatile("cp.async.commit_group;" ::: "memory");
}
__device__ __forceinline__ void cp_wait1() {
    asm volatile("cp.async.wait_group 1;" ::: "memory");
}
__device__ __forceinline__ void cp_wait0() {
    asm volatile("cp.async.wait_group 0;" ::: "memory");
}

// fp32 -> bf16 big + bf16 residual, packed as 2x half words
__device__ __forceinline__ void split2(float x, float y, uint32_t& bw, uint32_t& rw) {
    __nv_bfloat16 bx = __float2bfloat16_rn(x), by = __float2bfloat16_rn(y);
    float rx = x - __bfloat162float(bx), ry = y - __bfloat162float(by);
    __nv_bfloat16 cx = __float2bfloat16_rn(rx), cy = __float2bfloat16_rn(ry);
    bw = ((uint32_t)__bfloat16_as_ushort(by) << 16) | __bfloat16_as_ushort(bx);
    rw = ((uint32_t)__bfloat16_as_ushort(cy) << 16) | __bfloat16_as_ushort(cx);
}

// ---------------------------------------------------------------------------
// Scratch (static device globals)
// ---------------------------------------------------------------------------
__device__ __nv_bfloat16 g_xT_b[((size_t)kBN * kT * kHW + 64) * kCH];
__device__ __nv_bfloat16 g_xT_r[((size_t)kBN * kT * kHW + 64) * kCH];
__device__ float g_attn[(size_t)kNAtt * kHW * kHW];
__device__ __nv_bfloat16 g_attn_b[((size_t)kNAtt * kHW + 128) * kHW];
__device__ __nv_bfloat16 g_attn_r[((size_t)kNAtt * kHW + 128) * kHW];
__device__ float g_vspe[kBN * kT * kVCH * kHW];
__device__ __nv_bfloat16 g_acc0_b[((size_t)kNB * kCP + 128) * kHW];
__device__ __nv_bfloat16 g_acc0_r[((size_t)kNB * kCP + 128) * kHW];
__device__ __nv_bfloat16 g_acc1_b[((size_t)kNB * 2 * kCP + 128) * kHW];
__device__ __nv_bfloat16 g_acc1_r[((size_t)kNB * 2 * kCP + 128) * kHW];
__device__ __nv_bfloat16 g_acc2_b[((size_t)kNB * 3 * kCP + 128) * kHW];
__device__ __nv_bfloat16 g_acc2_r[((size_t)kNB * 3 * kCP + 128) * kHW];

__device__ __forceinline__ __nv_bfloat16* acc_b(int s) {
    return s == 0 ? g_acc0_b : (s == 1 ? g_acc1_b : g_acc2_b);
}
__device__ __forceinline__ __nv_bfloat16* acc_r(int s) {
    return s == 0 ? g_acc0_r : (s == 1 ? g_acc1_r : g_acc2_r);
}

// ---------------------------------------------------------------------------
// SMEM tile buffer (double-buffered, dynamic smem).  128(m) x 128(n) CTA tile.
// ---------------------------------------------------------------------------
struct Buf {
    __nv_bfloat16 Ab[128 * kLds];
    __nv_bfloat16 Ar[128 * kLds];
    __nv_bfloat16 Bb[128 * kLds];
    __nv_bfloat16 Br[128 * kLds];
};
constexpr int kSmemDyn = 2 * sizeof(Buf);  // 81920 B -> 2 CTAs/SM (smem-wise)

__device__ __forceinline__ void stage_tile(
    Buf& d, const __nv_bfloat16* __restrict__ Agb, const __nv_bfloat16* __restrict__ Agr,
    int lda, const __nv_bfloat16* __restrict__ Bgb, const __nv_bfloat16* __restrict__ Bgr,
    int ldb, int k0, int tid) {
#pragma unroll
    for (int s = 0; s < 8; s++) {
        int i = s * 256 + tid;        // 0..2047
        int row = (i >> 2) & 127, c = i & 3;
        int coff = c * 8;
        if (i < 512)
            cpasync16(&d.Ab[row * kLds + coff], Agb + (size_t)row * lda + k0 + coff);
        else if (i < 1024)
            cpasync16(&d.Ar[row * kLds + coff], Agr + (size_t)row * lda + k0 + coff);
        else if (i < 1536)
            cpasync16(&d.Bb[row * kLds + coff], Bgb + (size_t)row * ldb + k0 + coff);
        else
            cpasync16(&d.Br[row * kLds + coff], Bgr + (size_t)row * ldb + k0 + coff);
    }
}

// Core: C[128x128] accumulate over K (multiple of 32). 8 warps = 4(m) x 2(n),
// warp tile 32(m) x 64(n). Fragments via ldmatrix.x4.
__device__ __forceinline__ void gemm_core(
    const __nv_bfloat16* __restrict__ Agb, const __nv_bfloat16* __restrict__ Agr, int lda,
    const __nv_bfloat16* __restrict__ Bgb, const __nv_bfloat16* __restrict__ Bgr, int ldb,
    int K, float acc[2][8][4], Buf* bufs) {
    int tid = threadIdx.x;
    int wid = tid >> 5, lane = tid & 31;
    int wm = wid & 3, wn = wid >> 2;

    int j = lane >> 3, r = lane & 7;
    uint32_t aoff = (uint32_t)(((wm * 32 + ((j & 1) << 3) + r) * kLds + ((j >> 1) << 3)) * 2);
    uint32_t boff = (uint32_t)(((wn * 64 + ((j >> 1) << 3) + r) * kLds + ((j & 1) << 3)) * 2);

#pragma unroll
    for (int i = 0; i < 2; i++)
#pragma unroll
        for (int jj = 0; jj < 8; jj++)
#pragma unroll
            for (int q = 0; q < 4; q++) acc[i][jj][q] = 0.f;

    int nt = K / 32;
    stage_tile(bufs[0], Agb, Agr, lda, Bgb, Bgr, ldb, 0, tid);
    cp_commit();
    for (int kt = 0; kt < nt; kt++) {
        if (kt + 1 < nt) {
            stage_tile(bufs[(kt + 1) & 1], Agb, Agr, lda, Bgb, Bgr, ldb, (kt + 1) * 32, tid);
            cp_commit();
            cp_wait1();
        } else {
            cp_wait0();
        }
        __syncthreads();
        Buf& b = bufs[kt & 1];
        uint32_t Ab0 = smem_u32p(b.Ab) + aoff;
        uint32_t Ar0 = smem_u32p(b.Ar) + aoff;
        uint32_t Bb0 = smem_u32p(b.Bb) + boff;
        uint32_t Br0 = smem_u32p(b.Br) + boff;
#pragma unroll
        for (int kb = 0; kb < 2; kb++) {
            uint32_t kbb = kb * 32;  // 16 halves = 32 bytes
            uint32_t ab[2][4], ar[2][4];
            ldm_x4(ab[0], Ab0 + kbb);
            ldm_x4(ab[1], Ab0 + 16 * kLds * 2 + kbb);
            ldm_x4(ar[0], Ar0 + kbb);
            ldm_x4(ar[1], Ar0 + 16 * kLds * 2 + kbb);
#pragma unroll
            for (int half = 0; half < 2; half++) {
                uint32_t roff = (uint32_t)(half * 32 * kLds * 2) + kbb;
                uint32_t bbf[4][2], brf[4][2];
                {
                    uint32_t t[4];
                    ldm_x4(t, Bb0 + roff);
                    bbf[0][0] = t[0]; bbf[0][1] = t[1]; bbf[1][0] = t[2]; bbf[1][1] = t[3];
                    ldm_x4(t, Bb0 + roff + 16 * kLds * 2);
                    bbf[2][0] = t[0]; bbf[2][1] = t[1]; bbf[3][0] = t[2]; bbf[3][1] = t[3];
                    ldm_x4(t, Br0 + roff);
                    brf[0][0] = t[0]; brf[0][1] = t[1]; brf[1][0] = t[2]; brf[1][1] = t[3];
                    ldm_x4(t, Br0 + roff + 16 * kLds * 2);
                    brf[2][0] = t[0]; brf[2][1] = t[1]; brf[3][0] = t[2]; brf[3][1] = t[3];
                }
#pragma unroll
                for (int mi = 0; mi < 2; mi++)
#pragma unroll
                    for (int ni = 0; ni < 4; ni++) {
                        float* a = acc[mi][half * 4 + ni];
                        mma16816(a, ab[mi], bbf[ni]);
                        mma16816(a, ab[mi], brf[ni]);
                        mma16816(a, ar[mi], bbf[ni]);
                    }
            }
        }
        __syncthreads();
    }
}

// ---------------------------------------------------------------------------
// 1) Normalize + transpose + split: g_xT_{b,r}[bt*HW+pix][c]
// ---------------------------------------------------------------------------
__global__ __launch_bounds__(256) void normalize_t_kernel(const float* __restrict__ x) {
    __shared__ float sm[128][65];
    __shared__ float psum[4][64];
    __shared__ float invs[64];
    int bt = blockIdx.x, p0 = blockIdx.y * 64;
    int tid = threadIdx.x;
    int px = tid & 63, cq = tid >> 6;
    const float* xb = x + (size_t)bt * kCH * kHW + p0;
    float s = 0.f;
#pragma unroll
    for (int j = 0; j < 32; j++) {
        int c = cq * 32 + j;
        float v = xb[(size_t)c * kHW + px];
        sm[c][px] = v;
        s += v * v;
    }
    psum[cq][px] = s;
    __syncthreads();
    if (tid < 64) {
        float tot = psum[0][tid] + psum[1][tid] + psum[2][tid] + psum[3][tid];
        invs[tid] = 1.0f / fmaxf(sqrtf(tot), 1e-12f);
    }
    __syncthreads();
    float iv = invs[px];
    size_t rb = ((size_t)bt * kHW + p0 + px) * kCH + cq * 32;
#pragma unroll
    for (int j4 = 0; j4 < 8; j4++) {
        int c = cq * 32 + j4 * 4;
        float v0 = sm[c][px] * iv, v1 = sm[c + 1][px] * iv;
        float v2 = sm[c + 2][px] * iv, v3 = sm[c + 3][px] * iv;
        uint32_t bw0, rw0, bw1, rw1;
        split2(v0, v1, bw0, rw0);
        split2(v2, v3, bw1, rw1);
        *(uint2*)(g_xT_b + rb + j4 * 4) = make_uint2(bw0, bw1);
        *(uint2*)(g_xT_r + rb + j4 * 4) = make_uint2(rw0, rw1);
    }
}

// ---------------------------------------------------------------------------
// 2) Value projection (FFMA2 SIMT): vs_pe = Wv @ x + bv
// ---------------------------------------------------------------------------
__global__ __launch_bounds__(256) void vproj_kernel(const float* __restrict__ x,
                                                    const float* __restrict__ Wv,
                                                    const float* __restrict__ bv) {
    int bt = blockIdx.y;
    int p0 = blockIdx.x * 64;
    __shared__ __align__(16) float Ws[16][132];
    __shared__ __align__(16) float Xs[16][68];
    int tid = threadIdx.x;
    int ty = tid >> 4, tx = tid & 15;
    unsigned long long acc[4][4];
#pragma unroll
    for (int i = 0; i < 4; i++)
#pragma unroll
        for (int j = 0; j < 4; j++) acc[i][j] = 0ULL;

    const float* xb = x + (size_t)bt * kCH * kHW;
    for (int c0 = 0; c0 < kCH; c0 += 16) {
#pragma unroll
        for (int r = 0; r < 8; r++) {
            int lin = r * 256 + tid;
            int o = lin >> 4, c = lin & 15;
            Ws[c][o] = Wv[o * kCH + c0 + c];
        }
#pragma unroll
        for (int r = 0; r < 4; r++) {
            int lin = r * 256 + tid;
            int c = lin >> 6, j = lin & 63;
            Xs[c][j] = xb[(size_t)(c0 + c) * kHW + p0 + j];
        }
        __syncthreads();
#pragma unroll
        for (int c = 0; c < 16; c++) {
            float4 xv = *(const float4*)&Xs[c][tx * 4];
            float4 w0 = *(const float4*)&Ws[c][ty * 8];
            float4 w1 = *(const float4*)&Ws[c][ty * 8 + 4];
            unsigned long long wp[4] = {pack2(w0.x, w0.y), pack2(w0.z, w0.w),
                                        pack2(w1.x, w1.y), pack2(w1.z, w1.w)};
            unsigned long long xd[4] = {dup2(xv.x), dup2(xv.y), dup2(xv.z), dup2(xv.w)};
#pragma unroll
            for (int i = 0; i < 4; i++)
#pragma unroll
                for (int j = 0; j < 4; j++) ffma2(acc[i][j], wp[i], xd[j]);
        }
        __syncthreads();
    }
    float* ob = g_vspe + (size_t)bt * kVCH * kHW;
#pragma unroll
    for (int i = 0; i < 4; i++) {
        int o = ty * 8 + 2 * i;
        float b0 = bv[o], b1 = bv[o + 1];
#pragma unroll
        for (int j = 0; j < 4; j++) {
            float lo, hi;
            unpack2(acc[i][j], lo, hi);
            ob[(size_t)o * kHW + p0 + tx * 4 + j] = lo + b0;
            ob[(size_t)(o + 1) * kHW + p0 + tx * 4 + j] = hi + b1;
        }
    }
}

// ---------------------------------------------------------------------------
// 3) Positional-encoding channels 128..145 of vs_pe
// ---------------------------------------------------------------------------
__global__ __launch_bounds__(256) void pe_fill_kernel() {
    int gid = blockIdx.x * 256 + threadIdx.x;
    const int total = kBN * kT * 18 * kHW;
    if (gid >= total) return;
    int bt  = gid / (18 * kHW);
    int rem = gid % (18 * kHW);
    int c = rem / kHW, pix = rem % kHW;
    int yy = pix / kW, xx = pix % kW;
    float yc = -1.0f + 2.0f * (float)yy / (float)(kH - 1);
    float xc = -1.0f + 2.0f * (float)xx / (float)(kW - 1);
    float val;
    if (c == 0) val = yc;
    else if (c == 1) val = xc;
    else {
        int i = (c - 2) >> 2;
        int k = (c - 2) & 3;
        float coord = (k & 1) ? xc : yc;
        float f = (float)(1 << i) * 3.14159265358979323846f * coord;
        val = (k < 2) ? sinf(f) : cosf(f);
    }
    g_vspe[(size_t)bt * kVCH * kHW + (size_t)(kCH + c) * kHW + pix] = val;
}

// ---------------------------------------------------------------------------
// 4) Energy GEMM: grid = (5 n-tiles(128), 5 m-tiles(128), 176 g)
// ---------------------------------------------------------------------------
__global__ __launch_bounds__(256, 2) void energy_mma_kernel() {
    extern __shared__ __align__(16) char smem[];
    int g = blockIdx.z;
    int b = g / kTm1, t = g % kTm1;
    int m0 = blockIdx.y * 128, n0 = blockIdx.x * 128;
    size_t abase = ((size_t)(b * kT + t + 1) * kHW + m0) * kCH;
    size_t bbase = ((size_t)(b * kT + t) * kHW + n0) * kCH;
    float acc[2][8][4];
    gemm_core(g_xT_b + abase, g_xT_r + abase, kCH,
              g_xT_b + bbase, g_xT_r + bbase, kCH, kCH, acc, (Buf*)smem);

    int tid = threadIdx.x;
    int wid = tid >> 5, lane = tid & 31;
    int quad = lane >> 2, tq = lane & 3;
    int wm = wid & 3, wn = wid >> 2;
    int mvalid = kHW - m0;
    float* C = g_attn + (size_t)g * kHW * kHW + (size_t)m0 * kHW;
#pragma unroll
    for (int mi = 0; mi < 2; mi++)
#pragma unroll
        for (int rh = 0; rh < 2; rh++) {
            int rrow = wm * 32 + mi * 16 + quad + rh * 8;
            if (rrow < mvalid) {
#pragma unroll
                for (int ni = 0; ni < 8; ni++) {
                    int ncol = n0 + wn * 64 + ni * 8 + tq * 2;
                    if (ncol < kHW) {
                        float2 v = make_float2(acc[mi][ni][rh * 2] * kScale,
                                               acc[mi][ni][rh * 2 + 1] * kScale);
                        *(float2*)(C + (size_t)rrow * kHW + ncol) = v;
                    }
                }
            }
        }
}

// ---------------------------------------------------------------------------
// 5) Softmax row-wise; writes bf16 big/res pair
// ---------------------------------------------------------------------------
__global__ __launch_bounds__(256) void softmax_kernel() {
    size_t row = blockIdx.x;
    const float* p = g_attn + row * (size_t)kHW;
    int tid = threadIdx.x;
    int lane = tid & 31, wid = tid >> 5;
    __shared__ float redm[8], reds[8];

    float a = p[tid];
    float b = p[tid + 256];
    float c = (tid < 64) ? p[tid + 512] : -3.0e38f;
    float m = fmaxf(fmaxf(a, b), c);
#pragma unroll
    for (int off = 16; off > 0; off >>= 1) m = fmaxf(m, __shfl_xor_sync(0xffffffffu, m, off));
    if (lane == 0) redm[wid] = m;
    __syncthreads();
    float bm = redm[0];
#pragma unroll
    for (int w = 1; w < 8; w++) bm = fmaxf(bm, redm[w]);

    float e0 = expf(a - bm);
    float e1 = expf(b - bm);
    float e2 = (tid < 64) ? expf(c - bm) : 0.f;
    float s = e0 + e1 + e2;
#pragma unroll
    for (int off = 16; off > 0; off >>= 1) s += __shfl_xor_sync(0xffffffffu, s, off);
    if (lane == 0) reds[wid] = s;
    __syncthreads();
    float tot = reds[0];
#pragma unroll
    for (int w = 1; w < 8; w++) tot += reds[w];
    float inv = 1.0f / tot;

    __nv_bfloat16* ob = g_attn_b + row * (size_t)kHW;
    __nv_bfloat16* orr = g_attn_r + row * (size_t)kHW;
    float v0 = e0 * inv, v1 = e1 * inv;
    {
        __nv_bfloat16 b0 = __float2bfloat16_rn(v0);
        ob[tid] = b0;
        orr[tid] = __float2bfloat16_rn(v0 - __bfloat162float(b0));
        __nv_bfloat16 b1 = __float2bfloat16_rn(v1);
        ob[tid + 256] = b1;
        orr[tid + 256] = __float2bfloat16_rn(v1 - __bfloat162float(b1));
    }
    if (tid < 64) {
        float v2 = e2 * inv;
        __nv_bfloat16 b2 = __float2bfloat16_rn(v2);
        ob[tid + 512] = b2;
        orr[tid + 512] = __float2bfloat16_rn(v2 - __bfloat162float(b2));
    }
}

// ---------------------------------------------------------------------------
// 6) Copy "cs" slice from vs_pe. dstSel<3: bf16 pair; dstSel==3: fp32 out.
// ---------------------------------------------------------------------------
__global__ __launch_bounds__(256) void copy_cs_kernel(int dstSel, float* outp,
                                                      int dstC, int t0) {
    int gid = blockIdx.x * 256 + threadIdx.x;
    const int total = kNB * kCP * kHW;
    if (gid >= total) return;
    int bz = gid / (kCP * kHW);
    int rem = gid % (kCP * kHW);
    int c = rem / kHW, pix = rem % kHW;
    int b = bz / kTp, t = bz % kTp;
    float v = g_vspe[((size_t)b * kT + t + t0) * kVCH * kHW + (size_t)(kSSTA + c) * kHW + pix];
    size_t di = (size_t)bz * dstC * kHW + (size_t)c * kHW + pix;
    if (dstSel == 3) {
        outp[di] = v;
    } else {
        __nv_bfloat16 bb = __float2bfloat16_rn(v);
        acc_b(dstSel)[di] = bb;
        acc_r(dstSel)[di] = __float2bfloat16_rn(v - __bfloat162float(bb));
    }
}

// ---------------------------------------------------------------------------
// 7) Propagation GEMM: grid = (5 n-tiles(128), Mtiles(128), 144 bz)
// ---------------------------------------------------------------------------
__global__ __launch_bounds__(256, 2) void prop_mma_kernel(int dstSel, float* outp, int srcSel,
                                                          int dstC, int Cin, int t0) {
    extern __shared__ __align__(16) char smem[];
    int bz = blockIdx.z;
    int b = bz / kTp, t = bz % kTp;
    int c0 = blockIdx.y * 128, n0 = blockIdx.x * 128;
    size_t abase = ((size_t)bz * Cin + c0) * kHW;
    size_t bbase = ((size_t)b * kTm1 + t0 + t) * kHW * kHW + (size_t)n0 * kHW;
    float acc[2][8][4];
    gemm_core(acc_b(srcSel) + abase, acc_r(srcSel) + abase, kHW,
              g_attn_b + bbase, g_attn_r + bbase, kHW, kHW, acc, (Buf*)smem);

    int tid = threadIdx.x;
    int wid = tid >> 5, lane = tid & 31;
    int quad = lane >> 2, tq = lane & 3;
    int wm = wid & 3, wn = wid >> 2;
#pragma unroll
    for (int mi = 0; mi < 2; mi++)
#pragma unroll
        for (int rh = 0; rh < 2; rh++) {
            int rloc = wm * 32 + mi * 16 + quad + rh * 8;
            int cg = c0 + rloc;
            if (cg < Cin) {
                size_t rbase = ((size_t)bz * dstC + kCP + cg) * kHW;
#pragma unroll
                for (int ni = 0; ni < 8; ni++) {
                    int ncol = n0 + wn * 64 + ni * 8 + tq * 2;
                    if (ncol < kHW) {
                        if (dstSel == 3) {
                            float2 v = make_float2(acc[mi][ni][rh * 2],
                                                   acc[mi][ni][rh * 2 + 1]);
                            *(float2*)(outp + rbase + ncol) = v;
                        } else {
                            uint32_t bw, rw;
                            split2(acc[mi][ni][rh * 2], acc[mi][ni][rh * 2 + 1], bw, rw);
                            *(uint32_t*)(acc_b(dstSel) + rbase + ncol) = bw;
                            *(uint32_t*)(acc_r(dstSel) + rbase + ncol) = rw;
                        }
                    }
                }
            }
        }
}

// ---------------------------------------------------------------------------
extern "C" void kernel_launch(void* const* d_in, const int* in_sizes, int n_in,
                              void* d_out, int out_size) {
    const float* x  = (const float*)d_in[0];
    const float* Wv = (const float*)d_in[1];
    const float* bv = (const float*)d_in[2];
    float* out = (float*)d_out;

    static bool attrs_set = false;
    if (!attrs_set) {
        cudaFuncSetAttribute(energy_mma_kernel,
                             cudaFuncAttributeMaxDynamicSharedMemorySize, kSmemDyn);
        cudaFuncSetAttribute(prop_mma_kernel,
                             cudaFuncAttributeMaxDynamicSharedMemorySize, kSmemDyn);
        attrs_set = true;
    }

    normalize_t_kernel<<<dim3(kBN * kT, kHW / 64), 256>>>(x);
    vproj_kernel<<<dim3(kHW / 64, kBN * kT), 256>>>(x, Wv, bv);
    pe_fill_kernel<<<(kBN * kT * 18 * kHW + 255) / 256, 256>>>();
    energy_mma_kernel<<<dim3(5, 5, kNAtt), 256, kSmemDyn>>>();
    softmax_kernel<<<kNAtt * kHW, 256>>>();
    const int copyG = (kNB * kCP * kHW + 255) / 256;
    copy_cs_kernel<<<copyG, 256>>>(0, out, kCP, 0);
    prop_mma_kernel<<<dim3(5, 1, kNB), 256, kSmemDyn>>>(1, out, 0, 2 * kCP, kCP, 0);
    copy_cs_kernel<<<copyG, 256>>>(1, out, 2 * kCP, 1);
    prop_mma_kernel<<<dim3(5, 2, kNB), 256, kSmemDyn>>>(2, out, 1, 3 * kCP, 2 * kCP, 1);
    copy_cs_kernel<<<copyG, 256>>>(2, out, 3 * kCP, 2);
    prop_mma_kernel<<<dim3(5, 3, kNB), 256, kSmemDyn>>>(3, out, 2, 4 * kCP, 3 * kCP, 2);
    copy_cs_kernel<<<copyG, 256>>>(3, out, 4 * kCP, 3);
}

// round 9
// speedup vs baseline: 1.1298x; 1.1298x over previous
#include <cuda_runtime.h>
#include <cuda_fp16.h>
#include <math.h>
#include <cstdint>

// ---------------------------------------------------------------------------
// Problem constants (fixed by setup_inputs)
// ---------------------------------------------------------------------------
namespace {
constexpr int kBN   = 16;
constexpr int kT    = 12;
constexpr int kCH   = 128;
constexpr int kH    = 24, kW = 24;
constexpr int kHW   = 576;
constexpr int kTm1  = 11;
constexpr int kTp   = 9;
constexpr int kNB   = 144;    // kBN * kTp
constexpr int kVCH  = 146;
constexpr int kSSTA = 32;
constexpr int kCP   = 114;
constexpr int kNAtt = 176;    // kBN * kTm1
constexpr float kScale = 0.0883883476483184f;  // 128^-0.5
constexpr int kLds  = 40;     // smem row stride in halves (80 B, conflict-free)
}

// ---------------------------------------------------------------------------
// Low-level helpers
// ---------------------------------------------------------------------------
__device__ __forceinline__ unsigned long long pack2(float lo, float hi) {
    unsigned long long r;
    asm("mov.b64 %0, {%1, %2};" : "=l"(r) : "f"(lo), "f"(hi));
    return r;
}
__device__ __forceinline__ unsigned long long dup2(float v) { return pack2(v, v); }
__device__ __forceinline__ void ffma2(unsigned long long& d, unsigned long long a,
                                      unsigned long long b) {
    asm("fma.rn.f32x2 %0, %1, %2, %3;" : "=l"(d) : "l"(a), "l"(b), "l"(d));
}
__device__ __forceinline__ void unpack2(unsigned long long v, float& lo, float& hi) {
    asm("mov.b64 {%0, %1}, %2;" : "=f"(lo), "=f"(hi) : "l"(v));
}

// fp16 MMA m16n8k16 (legacy HMMA path -- valid on non-'a' sm_103 target)
__device__ __forceinline__ void mma16816(float* c, const uint32_t* a, const uint32_t* b) {
    asm volatile(
        "mma.sync.aligned.m16n8k16.row.col.f32.f16.f16.f32 "
        "{%0,%1,%2,%3}, {%4,%5,%6,%7}, {%8,%9}, {%0,%1,%2,%3};"
        : "+f"(c[0]), "+f"(c[1]), "+f"(c[2]), "+f"(c[3])
        : "r"(a[0]), "r"(a[1]), "r"(a[2]), "r"(a[3]), "r"(b[0]), "r"(b[1]));
}

__device__ __forceinline__ uint32_t smem_u32p(const void* p) {
    uint32_t a;
    asm("{ .reg .u64 t; cvta.to.shared.u64 t, %1; cvt.u32.u64 %0, t; }"
        : "=r"(a) : "l"(p));
    return a;
}
__device__ __forceinline__ void ldm_x4(uint32_t* r, uint32_t saddr) {
    asm volatile("ldmatrix.sync.aligned.m8n8.x4.shared.b16 {%0,%1,%2,%3}, [%4];"
                 : "=r"(r[0]), "=r"(r[1]), "=r"(r[2]), "=r"(r[3]) : "r"(saddr));
}
__device__ __forceinline__ void cpasync16(void* sdst, const void* gsrc) {
    asm volatile("cp.async.ca.shared.global [%0], [%1], 16;"
                 :: "r"(smem_u32p(sdst)), "l"(gsrc));
}
__device__ __forceinline__ void cp_commit() {
    asm volatile("cp.async.commit_group;" ::: "memory");
}
__device__ __forceinline__ void cp_wait1() {
    asm volatile("cp.async.wait_group 1;" ::: "memory");
}
__device__ __forceinline__ void cp_wait0() {
    asm volatile("cp.async.wait_group 0;" ::: "memory");
}

// fp32 -> fp16 big + fp16 residual, packed as 2x half words
__device__ __forceinline__ void split2h(float x, float y, uint32_t& hw, uint32_t& rw) {
    __half hx = __float2half_rn(x), hy = __float2half_rn(y);
    float rx = x - __half2float(hx), ry = y - __half2float(hy);
    __half cx = __float2half_rn(rx), cy = __float2half_rn(ry);
    hw = ((uint32_t)__half_as_ushort(hy) << 16) | __half_as_ushort(hx);
    rw = ((uint32_t)__half_as_ushort(cy) << 16) | __half_as_ushort(cx);
}

// ---------------------------------------------------------------------------
// Scratch (static device globals)
// ---------------------------------------------------------------------------
__device__ __half g_xT_b[((size_t)kBN * kT * kHW + 64) * kCH];
__device__ __half g_xT_r[((size_t)kBN * kT * kHW + 64) * kCH];
__device__ float g_attn[(size_t)kNAtt * kHW * kHW];     // energy out / softmax in
__device__ __half g_attn_h[((size_t)kNAtt * kHW + 64) * kHW];  // softmax out (single fp16)
__device__ float g_vspe[kBN * kT * kVCH * kHW];
__device__ __half g_acc0_b[((size_t)kNB * kCP + 128) * kHW];
__device__ __half g_acc0_r[((size_t)kNB * kCP + 128) * kHW];
__device__ __half g_acc1_b[((size_t)kNB * 2 * kCP + 128) * kHW];
__device__ __half g_acc1_r[((size_t)kNB * 2 * kCP + 128) * kHW];
__device__ __half g_acc2_b[((size_t)kNB * 3 * kCP + 128) * kHW];
__device__ __half g_acc2_r[((size_t)kNB * 3 * kCP + 128) * kHW];

__device__ __forceinline__ __half* acc_b(int s) {
    return s == 0 ? g_acc0_b : (s == 1 ? g_acc1_b : g_acc2_b);
}
__device__ __forceinline__ __half* acc_r(int s) {
    return s == 0 ? g_acc0_r : (s == 1 ? g_acc1_r : g_acc2_r);
}

// ---------------------------------------------------------------------------
// SMEM tile buffer (double-buffered).  128(m) x 64(n) CTA tile, split-2:
// A = big+res pair, B = big only.
// ---------------------------------------------------------------------------
struct Buf {
    __half Ab[128 * kLds];
    __half Ar[128 * kLds];
    __half Bh[64 * kLds];
};
constexpr int kSmemDyn = 2 * sizeof(Buf);  // 51200 B -> 3 CTAs/SM smem-wise

__device__ __forceinline__ void stage_tile(
    Buf& d, const __half* __restrict__ Agb, const __half* __restrict__ Agr, int lda,
    const __half* __restrict__ Bgh, int ldb, int k0, int tid) {
#pragma unroll
    for (int s = 0; s < 5; s++) {
        int i = s * 256 + tid;  // 0..1279
        int c = i & 3;
        int coff = c * 8;
        if (i < 512) {
            int row = i >> 2;
            cpasync16(&d.Ab[row * kLds + coff], Agb + (size_t)row * lda + k0 + coff);
        } else if (i < 1024) {
            int row = (i - 512) >> 2;
            cpasync16(&d.Ar[row * kLds + coff], Agr + (size_t)row * lda + k0 + coff);
        } else {
            int row = (i - 1024) >> 2;
            cpasync16(&d.Bh[row * kLds + coff], Bgh + (size_t)row * ldb + k0 + coff);
        }
    }
}

// Core: C[128x64] accumulate over K (multiple of 32). 8 warps = 4(m) x 2(n),
// warp tile 32x32. Fragments via ldmatrix.x4; split-2 (2 MMAs per frag set).
__device__ __forceinline__ void gemm_core(
    const __half* __restrict__ Agb, const __half* __restrict__ Agr, int lda,
    const __half* __restrict__ Bgh, int ldb,
    int K, float acc[2][4][4], Buf* bufs) {
    int tid = threadIdx.x;
    int wid = tid >> 5, lane = tid & 31;
    int wm = wid & 3, wn = wid >> 2;

    int j = lane >> 3, r = lane & 7;
    uint32_t aoff = (uint32_t)(((wm * 32 + ((j & 1) << 3) + r) * kLds + ((j >> 1) << 3)) * 2);
    uint32_t boff = (uint32_t)(((wn * 32 + ((j >> 1) << 3) + r) * kLds + ((j & 1) << 3)) * 2);

#pragma unroll
    for (int i = 0; i < 2; i++)
#pragma unroll
        for (int jj = 0; jj < 4; jj++)
#pragma unroll
            for (int q = 0; q < 4; q++) acc[i][jj][q] = 0.f;

    int nt = K / 32;
    stage_tile(bufs[0], Agb, Agr, lda, Bgh, ldb, 0, tid);
    cp_commit();
    for (int kt = 0; kt < nt; kt++) {
        if (kt + 1 < nt) {
            stage_tile(bufs[(kt + 1) & 1], Agb, Agr, lda, Bgh, ldb, (kt + 1) * 32, tid);
            cp_commit();
            cp_wait1();
        } else {
            cp_wait0();
        }
        __syncthreads();
        Buf& b = bufs[kt & 1];
        uint32_t Ab0 = smem_u32p(b.Ab) + aoff;
        uint32_t Ar0 = smem_u32p(b.Ar) + aoff;
        uint32_t Bh0 = smem_u32p(b.Bh) + boff;
#pragma unroll
        for (int kb = 0; kb < 2; kb++) {
            uint32_t kbb = kb * 32;  // 16 halves = 32 bytes
            uint32_t ab[2][4], ar[2][4];
            ldm_x4(ab[0], Ab0 + kbb);
            ldm_x4(ab[1], Ab0 + 16 * kLds * 2 + kbb);
            ldm_x4(ar[0], Ar0 + kbb);
            ldm_x4(ar[1], Ar0 + 16 * kLds * 2 + kbb);
            uint32_t bhf[4][2];
            {
                uint32_t t[4];
                ldm_x4(t, Bh0 + kbb);
                bhf[0][0] = t[0]; bhf[0][1] = t[1]; bhf[1][0] = t[2]; bhf[1][1] = t[3];
                ldm_x4(t, Bh0 + 16 * kLds * 2 + kbb);
                bhf[2][0] = t[0]; bhf[2][1] = t[1]; bhf[3][0] = t[2]; bhf[3][1] = t[3];
            }
#pragma unroll
            for (int mi = 0; mi < 2; mi++)
#pragma unroll
                for (int ni = 0; ni < 4; ni++) {
                    mma16816(acc[mi][ni], ab[mi], bhf[ni]);
                    mma16816(acc[mi][ni], ar[mi], bhf[ni]);
                }
        }
        __syncthreads();
    }
}

// ---------------------------------------------------------------------------
// 1) Normalize + transpose + split: g_xT_{b,r}[bt*HW+pix][c]
// ---------------------------------------------------------------------------
__global__ __launch_bounds__(256) void normalize_t_kernel(const float* __restrict__ x) {
    __shared__ float sm[128][65];
    __shared__ float psum[4][64];
    __shared__ float invs[64];
    int bt = blockIdx.x, p0 = blockIdx.y * 64;
    int tid = threadIdx.x;
    int px = tid & 63, cq = tid >> 6;
    const float* xb = x + (size_t)bt * kCH * kHW + p0;
    float s = 0.f;
#pragma unroll
    for (int j = 0; j < 32; j++) {
        int c = cq * 32 + j;
        float v = xb[(size_t)c * kHW + px];
        sm[c][px] = v;
        s += v * v;
    }
    psum[cq][px] = s;
    __syncthreads();
    if (tid < 64) {
        float tot = psum[0][tid] + psum[1][tid] + psum[2][tid] + psum[3][tid];
        invs[tid] = 1.0f / fmaxf(sqrtf(tot), 1e-12f);
    }
    __syncthreads();
    float iv = invs[px];
    size_t rb = ((size_t)bt * kHW + p0 + px) * kCH + cq * 32;
#pragma unroll
    for (int j4 = 0; j4 < 8; j4++) {
        int c = cq * 32 + j4 * 4;
        float v0 = sm[c][px] * iv, v1 = sm[c + 1][px] * iv;
        float v2 = sm[c + 2][px] * iv, v3 = sm[c + 3][px] * iv;
        uint32_t hw0, rw0, hw1, rw1;
        split2h(v0, v1, hw0, rw0);
        split2h(v2, v3, hw1, rw1);
        *(uint2*)(g_xT_b + rb + j4 * 4) = make_uint2(hw0, hw1);
        *(uint2*)(g_xT_r + rb + j4 * 4) = make_uint2(rw0, rw1);
    }
}

// ---------------------------------------------------------------------------
// 2) Value projection (FFMA2 SIMT): vs_pe = Wv @ x + bv
// ---------------------------------------------------------------------------
__global__ __launch_bounds__(256) void vproj_kernel(const float* __restrict__ x,
                                                    const float* __restrict__ Wv,
                                                    const float* __restrict__ bv) {
    int bt = blockIdx.y;
    int p0 = blockIdx.x * 64;
    __shared__ __align__(16) float Ws[16][132];
    __shared__ __align__(16) float Xs[16][68];
    int tid = threadIdx.x;
    int ty = tid >> 4, tx = tid & 15;
    unsigned long long acc[4][4];
#pragma unroll
    for (int i = 0; i < 4; i++)
#pragma unroll
        for (int j = 0; j < 4; j++) acc[i][j] = 0ULL;

    const float* xb = x + (size_t)bt * kCH * kHW;
    for (int c0 = 0; c0 < kCH; c0 += 16) {
#pragma unroll
        for (int r = 0; r < 8; r++) {
            int lin = r * 256 + tid;
            int o = lin >> 4, c = lin & 15;
            Ws[c][o] = Wv[o * kCH + c0 + c];
        }
#pragma unroll
        for (int r = 0; r < 4; r++) {
            int lin = r * 256 + tid;
            int c = lin >> 6, j = lin & 63;
            Xs[c][j] = xb[(size_t)(c0 + c) * kHW + p0 + j];
        }
        __syncthreads();
#pragma unroll
        for (int c = 0; c < 16; c++) {
            float4 xv = *(const float4*)&Xs[c][tx * 4];
            float4 w0 = *(const float4*)&Ws[c][ty * 8];
            float4 w1 = *(const float4*)&Ws[c][ty * 8 + 4];
            unsigned long long wp[4] = {pack2(w0.x, w0.y), pack2(w0.z, w0.w),
                                        pack2(w1.x, w1.y), pack2(w1.z, w1.w)};
            unsigned long long xd[4] = {dup2(xv.x), dup2(xv.y), dup2(xv.z), dup2(xv.w)};
#pragma unroll
            for (int i = 0; i < 4; i++)
#pragma unroll
                for (int j = 0; j < 4; j++) ffma2(acc[i][j], wp[i], xd[j]);
        }
        __syncthreads();
    }
    float* ob = g_vspe + (size_t)bt * kVCH * kHW;
#pragma unroll
    for (int i = 0; i < 4; i++) {
        int o = ty * 8 + 2 * i;
        float b0 = bv[o], b1 = bv[o + 1];
#pragma unroll
        for (int j = 0; j < 4; j++) {
            float lo, hi;
            unpack2(acc[i][j], lo, hi);
            ob[(size_t)o * kHW + p0 + tx * 4 + j] = lo + b0;
            ob[(size_t)(o + 1) * kHW + p0 + tx * 4 + j] = hi + b1;
        }
    }
}

// ---------------------------------------------------------------------------
// 3) Positional-encoding channels 128..145 of vs_pe
// ---------------------------------------------------------------------------
__global__ __launch_bounds__(256) void pe_fill_kernel() {
    int gid = blockIdx.x * 256 + threadIdx.x;
    const int total = kBN * kT * 18 * kHW;
    if (gid >= total) return;
    int bt  = gid / (18 * kHW);
    int rem = gid % (18 * kHW);
    int c = rem / kHW, pix = rem % kHW;
    int yy = pix / kW, xx = pix % kW;
    float yc = -1.0f + 2.0f * (float)yy / (float)(kH - 1);
    float xc = -1.0f + 2.0f * (float)xx / (float)(kW - 1);
    float val;
    if (c == 0) val = yc;
    else if (c == 1) val = xc;
    else {
        int i = (c - 2) >> 2;
        int k = (c - 2) & 3;
        float coord = (k & 1) ? xc : yc;
        float f = (float)(1 << i) * 3.14159265358979323846f * coord;
        val = (k < 2) ? sinf(f) : cosf(f);
    }
    g_vspe[(size_t)bt * kVCH * kHW + (size_t)(kCH + c) * kHW + pix] = val;
}

// ---------------------------------------------------------------------------
// 4) Energy GEMM: e[g,n,m] = scale * sum_c qT[n,c]*kT[m,c]; out fp32.
//    grid = (9 m-tiles(64), 5 n-tiles(128), 176 g).  B operand = xT big half.
// ---------------------------------------------------------------------------
__global__ __launch_bounds__(256) void energy_mma_kernel() {
    extern __shared__ __align__(16) char smem[];
    int g = blockIdx.z;
    int b = g / kTm1, t = g % kTm1;
    int m0 = blockIdx.y * 128, n0 = blockIdx.x * 64;
    size_t abase = ((size_t)(b * kT + t + 1) * kHW + m0) * kCH;
    size_t bbase = ((size_t)(b * kT + t) * kHW + n0) * kCH;
    float acc[2][4][4];
    gemm_core(g_xT_b + abase, g_xT_r + abase, kCH,
              g_xT_b + bbase, kCH, kCH, acc, (Buf*)smem);

    int tid = threadIdx.x;
    int wid = tid >> 5, lane = tid & 31;
    int quad = lane >> 2, tq = lane & 3;
    int wm = wid & 3, wn = wid >> 2;
    int mvalid = kHW - m0;
    float* C = g_attn + (size_t)g * kHW * kHW + (size_t)m0 * kHW + n0;
#pragma unroll
    for (int mi = 0; mi < 2; mi++)
#pragma unroll
        for (int rh = 0; rh < 2; rh++) {
            int rrow = wm * 32 + mi * 16 + quad + rh * 8;
            if (rrow < mvalid) {
#pragma unroll
                for (int ni = 0; ni < 4; ni++) {
                    float2 v = make_float2(acc[mi][ni][rh * 2] * kScale,
                                           acc[mi][ni][rh * 2 + 1] * kScale);
                    *(float2*)(C + (size_t)rrow * kHW + wn * 32 + ni * 8 + tq * 2) = v;
                }
            }
        }
}

// ---------------------------------------------------------------------------
// 5) Softmax row-wise; writes single fp16 attn
// ---------------------------------------------------------------------------
__global__ __launch_bounds__(256) void softmax_kernel() {
    size_t row = blockIdx.x;
    const float* p = g_attn + row * (size_t)kHW;
    int tid = threadIdx.x;
    int lane = tid & 31, wid = tid >> 5;
    __shared__ float redm[8], reds[8];

    float a = p[tid];
    float b = p[tid + 256];
    float c = (tid < 64) ? p[tid + 512] : -3.0e38f;
    float m = fmaxf(fmaxf(a, b), c);
#pragma unroll
    for (int off = 16; off > 0; off >>= 1) m = fmaxf(m, __shfl_xor_sync(0xffffffffu, m, off));
    if (lane == 0) redm[wid] = m;
    __syncthreads();
    float bm = redm[0];
#pragma unroll
    for (int w = 1; w < 8; w++) bm = fmaxf(bm, redm[w]);

    float e0 = expf(a - bm);
    float e1 = expf(b - bm);
    float e2 = (tid < 64) ? expf(c - bm) : 0.f;
    float s = e0 + e1 + e2;
#pragma unroll
    for (int off = 16; off > 0; off >>= 1) s += __shfl_xor_sync(0xffffffffu, s, off);
    if (lane == 0) reds[wid] = s;
    __syncthreads();
    float tot = reds[0];
#pragma unroll
    for (int w = 1; w < 8; w++) tot += reds[w];
    float inv = 1.0f / tot;

    __half* oh = g_attn_h + row * (size_t)kHW;
    oh[tid] = __float2half_rn(e0 * inv);
    oh[tid + 256] = __float2half_rn(e1 * inv);
    if (tid < 64) oh[tid + 512] = __float2half_rn(e2 * inv);
}

// ---------------------------------------------------------------------------
// 6) Copy "cs" slice from vs_pe. dstSel<3: fp16 pair; dstSel==3: fp32 out.
// ---------------------------------------------------------------------------
__global__ __launch_bounds__(256) void copy_cs_kernel(int dstSel, float* outp,
                                                      int dstC, int t0) {
    int gid = blockIdx.x * 256 + threadIdx.x;
    const int total = kNB * kCP * kHW;
    if (gid >= total) return;
    int bz = gid / (kCP * kHW);
    int rem = gid % (kCP * kHW);
    int c = rem / kHW, pix = rem % kHW;
    int b = bz / kTp, t = bz % kTp;
    float v = g_vspe[((size_t)b * kT + t + t0) * kVCH * kHW + (size_t)(kSSTA + c) * kHW + pix];
    size_t di = (size_t)bz * dstC * kHW + (size_t)c * kHW + pix;
    if (dstSel == 3) {
        outp[di] = v;
    } else {
        __half hh = __float2half_rn(v);
        acc_b(dstSel)[di] = hh;
        acc_r(dstSel)[di] = __float2half_rn(v - __half2float(hh));
    }
}

// ---------------------------------------------------------------------------
// 7) Propagation GEMM: dst[bz,114+c,n] = sum_m A[bz,c,m]*attn[b,t0+t,n,m]
//    grid = (9 n-tiles(64), Mtiles(128), 144 bz). B operand = attn fp16.
// ---------------------------------------------------------------------------
__global__ __launch_bounds__(256) void prop_mma_kernel(int dstSel, float* outp, int srcSel,
                                                       int dstC, int Cin, int t0) {
    extern __shared__ __align__(16) char smem[];
    int bz = blockIdx.z;
    int b = bz / kTp, t = bz % kTp;
    int c0 = blockIdx.y * 128, n0 = blockIdx.x * 64;
    size_t abase = ((size_t)bz * Cin + c0) * kHW;
    size_t bbase = ((size_t)b * kTm1 + t0 + t) * kHW * kHW + (size_t)n0 * kHW;
    float acc[2][4][4];
    gemm_core(acc_b(srcSel) + abase, acc_r(srcSel) + abase, kHW,
              g_attn_h + bbase, kHW, kHW, acc, (Buf*)smem);

    int tid = threadIdx.x;
    int wid = tid >> 5, lane = tid & 31;
    int quad = lane >> 2, tq = lane & 3;
    int wm = wid & 3, wn = wid >> 2;
#pragma unroll
    for (int mi = 0; mi < 2; mi++)
#pragma unroll
        for (int rh = 0; rh < 2; rh++) {
            int rloc = wm * 32 + mi * 16 + quad + rh * 8;
            int cg = c0 + rloc;
            if (cg < Cin) {
                size_t di = ((size_t)bz * dstC + kCP + cg) * kHW + n0 + wn * 32 + tq * 2;
                if (dstSel == 3) {
#pragma unroll
                    for (int ni = 0; ni < 4; ni++) {
                        float2 v = make_float2(acc[mi][ni][rh * 2], acc[mi][ni][rh * 2 + 1]);
                        *(float2*)(outp + di + ni * 8) = v;
                    }
                } else {
                    __half* db = acc_b(dstSel);
                    __half* dr = acc_r(dstSel);
#pragma unroll
                    for (int ni = 0; ni < 4; ni++) {
                        uint32_t hw, rw;
                        split2h(acc[mi][ni][rh * 2], acc[mi][ni][rh * 2 + 1], hw, rw);
                        *(uint32_t*)(db + di + ni * 8) = hw;
                        *(uint32_t*)(dr + di + ni * 8) = rw;
                    }
                }
            }
        }
}

// ---------------------------------------------------------------------------
extern "C" void kernel_launch(void* const* d_in, const int* in_sizes, int n_in,
                              void* d_out, int out_size) {
    const float* x  = (const float*)d_in[0];
    const float* Wv = (const float*)d_in[1];
    const float* bv = (const float*)d_in[2];
    float* out = (float*)d_out;

    static bool attrs_set = false;
    if (!attrs_set) {
        cudaFuncSetAttribute(energy_mma_kernel,
                             cudaFuncAttributeMaxDynamicSharedMemorySize, kSmemDyn);
        cudaFuncSetAttribute(prop_mma_kernel,
                             cudaFuncAttributeMaxDynamicSharedMemorySize, kSmemDyn);
        attrs_set = true;
    }

    normalize_t_kernel<<<dim3(kBN * kT, kHW / 64), 256>>>(x);
    vproj_kernel<<<dim3(kHW / 64, kBN * kT), 256>>>(x, Wv, bv);
    pe_fill_kernel<<<(kBN * kT * 18 * kHW + 255) / 256, 256>>>();
    energy_mma_kernel<<<dim3(9, 5, kNAtt), 256, kSmemDyn>>>();
    softmax_kernel<<<kNAtt * kHW, 256>>>();
    const int copyG = (kNB * kCP * kHW + 255) / 256;
    copy_cs_kernel<<<copyG, 256>>>(0, out, kCP, 0);
    prop_mma_kernel<<<dim3(9, 1, kNB), 256, kSmemDyn>>>(1, out, 0, 2 * kCP, kCP, 0);
    copy_cs_kernel<<<copyG, 256>>>(1, out, 2 * kCP, 1);
    prop_mma_kernel<<<dim3(9, 2, kNB), 256, kSmemDyn>>>(2, out, 1, 3 * kCP, 2 * kCP, 1);
    copy_cs_kernel<<<copyG, 256>>>(2, out, 3 * kCP, 2);
    prop_mma_kernel<<<dim3(9, 3, kNB), 256, kSmemDyn>>>(3, out, 2, 4 * kCP, 3 * kCP, 2);
    copy_cs_kernel<<<copyG, 256>>>(3, out, 4 * kCP, 3);
}

// round 10
// speedup vs baseline: 1.6854x; 1.4918x over previous
#include <cuda_runtime.h>
#include <cuda_fp16.h>
#include <math.h>
#include <cstdint>

// ---------------------------------------------------------------------------
// Problem constants (fixed by setup_inputs)
// ---------------------------------------------------------------------------
namespace {
constexpr int kBN   = 16;
constexpr int kT    = 12;
constexpr int kCH   = 128;
constexpr int kH    = 24, kW = 24;
constexpr int kHW   = 576;
constexpr int kTm1  = 11;
constexpr int kTp   = 9;
constexpr int kNB   = 144;    // kBN * kTp
constexpr int kVCH  = 146;
constexpr int kSSTA = 32;
constexpr int kCP   = 114;
constexpr int kNAtt = 176;    // kBN * kTm1
constexpr float kScale = 0.0883883476483184f;  // 128^-0.5
constexpr int kLds  = 40;     // smem row stride in halves (80 B, conflict-free)
}

// ---------------------------------------------------------------------------
// Low-level helpers
// ---------------------------------------------------------------------------
__device__ __forceinline__ unsigned long long pack2(float lo, float hi) {
    unsigned long long r;
    asm("mov.b64 %0, {%1, %2};" : "=l"(r) : "f"(lo), "f"(hi));
    return r;
}
__device__ __forceinline__ unsigned long long dup2(float v) { return pack2(v, v); }
__device__ __forceinline__ void ffma2(unsigned long long& d, unsigned long long a,
                                      unsigned long long b) {
    asm("fma.rn.f32x2 %0, %1, %2, %3;" : "=l"(d) : "l"(a), "l"(b), "l"(d));
}
__device__ __forceinline__ void unpack2(unsigned long long v, float& lo, float& hi) {
    asm("mov.b64 {%0, %1}, %2;" : "=f"(lo), "=f"(hi) : "l"(v));
}

// fp16 MMA m16n8k16 (legacy HMMA path -- valid on non-'a' sm_103 target)
__device__ __forceinline__ void mma16816(float* c, const uint32_t* a, const uint32_t* b) {
    asm volatile(
        "mma.sync.aligned.m16n8k16.row.col.f32.f16.f16.f32 "
        "{%0,%1,%2,%3}, {%4,%5,%6,%7}, {%8,%9}, {%0,%1,%2,%3};"
        : "+f"(c[0]), "+f"(c[1]), "+f"(c[2]), "+f"(c[3])
        : "r"(a[0]), "r"(a[1]), "r"(a[2]), "r"(a[3]), "r"(b[0]), "r"(b[1]));
}

__device__ __forceinline__ uint32_t smem_u32p(const void* p) {
    uint32_t a;
    asm("{ .reg .u64 t; cvta.to.shared.u64 t, %1; cvt.u32.u64 %0, t; }"
        : "=r"(a) : "l"(p));
    return a;
}
__device__ __forceinline__ void ldm_x4(uint32_t* r, uint32_t saddr) {
    asm volatile("ldmatrix.sync.aligned.m8n8.x4.shared.b16 {%0,%1,%2,%3}, [%4];"
                 : "=r"(r[0]), "=r"(r[1]), "=r"(r[2]), "=r"(r[3]) : "r"(saddr));
}
__device__ __forceinline__ void cpasync16(void* sdst, const void* gsrc) {
    asm volatile("cp.async.ca.shared.global [%0], [%1], 16;"
                 :: "r"(smem_u32p(sdst)), "l"(gsrc));
}
__device__ __forceinline__ void cp_commit() {
    asm volatile("cp.async.commit_group;" ::: "memory");
}
__device__ __forceinline__ void cp_wait1() {
    asm volatile("cp.async.wait_group 1;" ::: "memory");
}
__device__ __forceinline__ void cp_wait0() {
    asm volatile("cp.async.wait_group 0;" ::: "memory");
}

// fp32 -> fp16 big + fp16 residual, packed as 2x half words
__device__ __forceinline__ void split2h(float x, float y, uint32_t& hw, uint32_t& rw) {
    __half hx = __float2half_rn(x), hy = __float2half_rn(y);
    float rx = x - __half2float(hx), ry = y - __half2float(hy);
    __half cx = __float2half_rn(rx), cy = __float2half_rn(ry);
    hw = ((uint32_t)__half_as_ushort(hy) << 16) | __half_as_ushort(hx);
    rw = ((uint32_t)__half_as_ushort(cy) << 16) | __half_as_ushort(cx);
}

// ---------------------------------------------------------------------------
// Scratch (static device globals)
// ---------------------------------------------------------------------------
__device__ __half g_xT_b[((size_t)kBN * kT * kHW + 64) * kCH];
__device__ __half g_xT_r[((size_t)kBN * kT * kHW + 64) * kCH];
__device__ float g_attn[(size_t)kNAtt * kHW * kHW];     // energy out / softmax in
__device__ __half g_attn_h[((size_t)kNAtt * kHW + 64) * kHW];  // softmax out (single fp16)
__device__ float g_vspe[kBN * kT * kVCH * kHW];
__device__ __half g_acc0_b[((size_t)kNB * kCP + 128) * kHW];
__device__ __half g_acc0_r[((size_t)kNB * kCP + 128) * kHW];
__device__ __half g_acc1_b[((size_t)kNB * 2 * kCP + 128) * kHW];
__device__ __half g_acc1_r[((size_t)kNB * 2 * kCP + 128) * kHW];
__device__ __half g_acc2_b[((size_t)kNB * 3 * kCP + 128) * kHW];
__device__ __half g_acc2_r[((size_t)kNB * 3 * kCP + 128) * kHW];

__device__ __forceinline__ __half* acc_b(int s) {
    return s == 0 ? g_acc0_b : (s == 1 ? g_acc1_b : g_acc2_b);
}
__device__ __forceinline__ __half* acc_r(int s) {
    return s == 0 ? g_acc0_r : (s == 1 ? g_acc1_r : g_acc2_r);
}

// ---------------------------------------------------------------------------
// SMEM tile buffer (double-buffered).  128(m) x 64(n) CTA tile, split-2:
// A = big+res pair, B = big only.
// pad[] caps occupancy at 3 CTAs/SM (2*29184 = 58368 B > 228KB/4): the 4-CTA
// configuration (R9) lost to cross-CTA L1tex contention.
// ---------------------------------------------------------------------------
struct Buf {
    __half Ab[128 * kLds];
    __half Ar[128 * kLds];
    __half Bh[64 * kLds];
    char pad[3584];
};
constexpr int kSmemDyn = 2 * sizeof(Buf);  // 58368 B -> exactly 3 CTAs/SM

__device__ __forceinline__ void stage_tile(
    Buf& d, const __half* __restrict__ Agb, const __half* __restrict__ Agr, int lda,
    const __half* __restrict__ Bgh, int ldb, int k0, int tid) {
#pragma unroll
    for (int s = 0; s < 5; s++) {
        int i = s * 256 + tid;  // 0..1279
        int c = i & 3;
        int coff = c * 8;
        if (i < 512) {
            int row = i >> 2;
            cpasync16(&d.Ab[row * kLds + coff], Agb + (size_t)row * lda + k0 + coff);
        } else if (i < 1024) {
            int row = (i - 512) >> 2;
            cpasync16(&d.Ar[row * kLds + coff], Agr + (size_t)row * lda + k0 + coff);
        } else {
            int row = (i - 1024) >> 2;
            cpasync16(&d.Bh[row * kLds + coff], Bgh + (size_t)row * ldb + k0 + coff);
        }
    }
}

// Core: C[128x64] accumulate over K (multiple of 32). 8 warps = 4(m) x 2(n),
// warp tile 32x32. Fragments via ldmatrix.x4; split-2 (2 MMAs per frag set).
__device__ __forceinline__ void gemm_core(
    const __half* __restrict__ Agb, const __half* __restrict__ Agr, int lda,
    const __half* __restrict__ Bgh, int ldb,
    int K, float acc[2][4][4], Buf* bufs) {
    int tid = threadIdx.x;
    int wid = tid >> 5, lane = tid & 31;
    int wm = wid & 3, wn = wid >> 2;

    int j = lane >> 3, r = lane & 7;
    uint32_t aoff = (uint32_t)(((wm * 32 + ((j & 1) << 3) + r) * kLds + ((j >> 1) << 3)) * 2);
    uint32_t boff = (uint32_t)(((wn * 32 + ((j >> 1) << 3) + r) * kLds + ((j & 1) << 3)) * 2);

#pragma unroll
    for (int i = 0; i < 2; i++)
#pragma unroll
        for (int jj = 0; jj < 4; jj++)
#pragma unroll
            for (int q = 0; q < 4; q++) acc[i][jj][q] = 0.f;

    int nt = K / 32;
    stage_tile(bufs[0], Agb, Agr, lda, Bgh, ldb, 0, tid);
    cp_commit();
    for (int kt = 0; kt < nt; kt++) {
        if (kt + 1 < nt) {
            stage_tile(bufs[(kt + 1) & 1], Agb, Agr, lda, Bgh, ldb, (kt + 1) * 32, tid);
            cp_commit();
            cp_wait1();
        } else {
            cp_wait0();
        }
        __syncthreads();
        Buf& b = bufs[kt & 1];
        uint32_t Ab0 = smem_u32p(b.Ab) + aoff;
        uint32_t Ar0 = smem_u32p(b.Ar) + aoff;
        uint32_t Bh0 = smem_u32p(b.Bh) + boff;
#pragma unroll
        for (int kb = 0; kb < 2; kb++) {
            uint32_t kbb = kb * 32;  // 16 halves = 32 bytes
            uint32_t ab[2][4], ar[2][4];
            ldm_x4(ab[0], Ab0 + kbb);
            ldm_x4(ab[1], Ab0 + 16 * kLds * 2 + kbb);
            ldm_x4(ar[0], Ar0 + kbb);
            ldm_x4(ar[1], Ar0 + 16 * kLds * 2 + kbb);
            uint32_t bhf[4][2];
            {
                uint32_t t[4];
                ldm_x4(t, Bh0 + kbb);
                bhf[0][0] = t[0]; bhf[0][1] = t[1]; bhf[1][0] = t[2]; bhf[1][1] = t[3];
                ldm_x4(t, Bh0 + 16 * kLds * 2 + kbb);
                bhf[2][0] = t[0]; bhf[2][1] = t[1]; bhf[3][0] = t[2]; bhf[3][1] = t[3];
            }
#pragma unroll
            for (int mi = 0; mi < 2; mi++)
#pragma unroll
                for (int ni = 0; ni < 4; ni++) {
                    mma16816(acc[mi][ni], ab[mi], bhf[ni]);
                    mma16816(acc[mi][ni], ar[mi], bhf[ni]);
                }
        }
        __syncthreads();
    }
}

// ---------------------------------------------------------------------------
// 1) Normalize + transpose + split: g_xT_{b,r}[bt*HW+pix][c]
// ---------------------------------------------------------------------------
__global__ __launch_bounds__(256) void normalize_t_kernel(const float* __restrict__ x) {
    __shared__ float sm[128][65];
    __shared__ float psum[4][64];
    __shared__ float invs[64];
    int bt = blockIdx.x, p0 = blockIdx.y * 64;
    int tid = threadIdx.x;
    int px = tid & 63, cq = tid >> 6;
    const float* xb = x + (size_t)bt * kCH * kHW + p0;
    float s = 0.f;
#pragma unroll
    for (int j = 0; j < 32; j++) {
        int c = cq * 32 + j;
        float v = xb[(size_t)c * kHW + px];
        sm[c][px] = v;
        s += v * v;
    }
    psum[cq][px] = s;
    __syncthreads();
    if (tid < 64) {
        float tot = psum[0][tid] + psum[1][tid] + psum[2][tid] + psum[3][tid];
        invs[tid] = 1.0f / fmaxf(sqrtf(tot), 1e-12f);
    }
    __syncthreads();
    float iv = invs[px];
    size_t rb = ((size_t)bt * kHW + p0 + px) * kCH + cq * 32;
#pragma unroll
    for (int j4 = 0; j4 < 8; j4++) {
        int c = cq * 32 + j4 * 4;
        float v0 = sm[c][px] * iv, v1 = sm[c + 1][px] * iv;
        float v2 = sm[c + 2][px] * iv, v3 = sm[c + 3][px] * iv;
        uint32_t hw0, rw0, hw1, rw1;
        split2h(v0, v1, hw0, rw0);
        split2h(v2, v3, hw1, rw1);
        *(uint2*)(g_xT_b + rb + j4 * 4) = make_uint2(hw0, hw1);
        *(uint2*)(g_xT_r + rb + j4 * 4) = make_uint2(rw0, rw1);
    }
}

// ---------------------------------------------------------------------------
// 2) Value projection (FFMA2 SIMT): vs_pe = Wv @ x + bv
// ---------------------------------------------------------------------------
__global__ __launch_bounds__(256) void vproj_kernel(const float* __restrict__ x,
                                                    const float* __restrict__ Wv,
                                                    const float* __restrict__ bv) {
    int bt = blockIdx.y;
    int p0 = blockIdx.x * 64;
    __shared__ __align__(16) float Ws[16][132];
    __shared__ __align__(16) float Xs[16][68];
    int tid = threadIdx.x;
    int ty = tid >> 4, tx = tid & 15;
    unsigned long long acc[4][4];
#pragma unroll
    for (int i = 0; i < 4; i++)
#pragma unroll
        for (int j = 0; j < 4; j++) acc[i][j] = 0ULL;

    const float* xb = x + (size_t)bt * kCH * kHW;
    for (int c0 = 0; c0 < kCH; c0 += 16) {
#pragma unroll
        for (int r = 0; r < 8; r++) {
            int lin = r * 256 + tid;
            int o = lin >> 4, c = lin & 15;
            Ws[c][o] = Wv[o * kCH + c0 + c];
        }
#pragma unroll
        for (int r = 0; r < 4; r++) {
            int lin = r * 256 + tid;
            int c = lin >> 6, j = lin & 63;
            Xs[c][j] = xb[(size_t)(c0 + c) * kHW + p0 + j];
        }
        __syncthreads();
#pragma unroll
        for (int c = 0; c < 16; c++) {
            float4 xv = *(const float4*)&Xs[c][tx * 4];
            float4 w0 = *(const float4*)&Ws[c][ty * 8];
            float4 w1 = *(const float4*)&Ws[c][ty * 8 + 4];
            unsigned long long wp[4] = {pack2(w0.x, w0.y), pack2(w0.z, w0.w),
                                        pack2(w1.x, w1.y), pack2(w1.z, w1.w)};
            unsigned long long xd[4] = {dup2(xv.x), dup2(xv.y), dup2(xv.z), dup2(xv.w)};
#pragma unroll
            for (int i = 0; i < 4; i++)
#pragma unroll
                for (int j = 0; j < 4; j++) ffma2(acc[i][j], wp[i], xd[j]);
        }
        __syncthreads();
    }
    float* ob = g_vspe + (size_t)bt * kVCH * kHW;
#pragma unroll
    for (int i = 0; i < 4; i++) {
        int o = ty * 8 + 2 * i;
        float b0 = bv[o], b1 = bv[o + 1];
#pragma unroll
        for (int j = 0; j < 4; j++) {
            float lo, hi;
            unpack2(acc[i][j], lo, hi);
            ob[(size_t)o * kHW + p0 + tx * 4 + j] = lo + b0;
            ob[(size_t)(o + 1) * kHW + p0 + tx * 4 + j] = hi + b1;
        }
    }
}

// ---------------------------------------------------------------------------
// 3) Positional-encoding channels 128..145 of vs_pe
// ---------------------------------------------------------------------------
__global__ __launch_bounds__(256) void pe_fill_kernel() {
    int gid = blockIdx.x * 256 + threadIdx.x;
    const int total = kBN * kT * 18 * kHW;
    if (gid >= total) return;
    int bt  = gid / (18 * kHW);
    int rem = gid % (18 * kHW);
    int c = rem / kHW, pix = rem % kHW;
    int yy = pix / kW, xx = pix % kW;
    float yc = -1.0f + 2.0f * (float)yy / (float)(kH - 1);
    float xc = -1.0f + 2.0f * (float)xx / (float)(kW - 1);
    float val;
    if (c == 0) val = yc;
    else if (c == 1) val = xc;
    else {
        int i = (c - 2) >> 2;
        int k = (c - 2) & 3;
        float coord = (k & 1) ? xc : yc;
        float f = (float)(1 << i) * 3.14159265358979323846f * coord;
        val = (k < 2) ? sinf(f) : cosf(f);
    }
    g_vspe[(size_t)bt * kVCH * kHW + (size_t)(kCH + c) * kHW + pix] = val;
}

// ---------------------------------------------------------------------------
// 4) Energy GEMM: e[g,n,m] = scale * sum_c qT[n,c]*kT[m,c]; out fp32.
//    grid = (9 m-tiles(64), 5 n-tiles(128), 176 g).  B operand = xT big half.
// ---------------------------------------------------------------------------
__global__ __launch_bounds__(256) void energy_mma_kernel() {
    extern __shared__ __align__(16) char smem[];
    int g = blockIdx.z;
    int b = g / kTm1, t = g % kTm1;
    int m0 = blockIdx.y * 128, n0 = blockIdx.x * 64;
    size_t abase = ((size_t)(b * kT + t + 1) * kHW + m0) * kCH;
    size_t bbase = ((size_t)(b * kT + t) * kHW + n0) * kCH;
    float acc[2][4][4];
    gemm_core(g_xT_b + abase, g_xT_r + abase, kCH,
              g_xT_b + bbase, kCH, kCH, acc, (Buf*)smem);

    int tid = threadIdx.x;
    int wid = tid >> 5, lane = tid & 31;
    int quad = lane >> 2, tq = lane & 3;
    int wm = wid & 3, wn = wid >> 2;
    int mvalid = kHW - m0;
    float* C = g_attn + (size_t)g * kHW * kHW + (size_t)m0 * kHW + n0;
#pragma unroll
    for (int mi = 0; mi < 2; mi++)
#pragma unroll
        for (int rh = 0; rh < 2; rh++) {
            int rrow = wm * 32 + mi * 16 + quad + rh * 8;
            if (rrow < mvalid) {
#pragma unroll
                for (int ni = 0; ni < 4; ni++) {
                    float2 v = make_float2(acc[mi][ni][rh * 2] * kScale,
                                           acc[mi][ni][rh * 2 + 1] * kScale);
                    *(float2*)(C + (size_t)rrow * kHW + wn * 32 + ni * 8 + tq * 2) = v;
                }
            }
        }
}

// ---------------------------------------------------------------------------
// 5) Softmax row-wise; writes single fp16 attn
// ---------------------------------------------------------------------------
__global__ __launch_bounds__(256) void softmax_kernel() {
    size_t row = blockIdx.x;
    const float* p = g_attn + row * (size_t)kHW;
    int tid = threadIdx.x;
    int lane = tid & 31, wid = tid >> 5;
    __shared__ float redm[8], reds[8];

    float a = p[tid];
    float b = p[tid + 256];
    float c = (tid < 64) ? p[tid + 512] : -3.0e38f;
    float m = fmaxf(fmaxf(a, b), c);
#pragma unroll
    for (int off = 16; off > 0; off >>= 1) m = fmaxf(m, __shfl_xor_sync(0xffffffffu, m, off));
    if (lane == 0) redm[wid] = m;
    __syncthreads();
    float bm = redm[0];
#pragma unroll
    for (int w = 1; w < 8; w++) bm = fmaxf(bm, redm[w]);

    float e0 = expf(a - bm);
    float e1 = expf(b - bm);
    float e2 = (tid < 64) ? expf(c - bm) : 0.f;
    float s = e0 + e1 + e2;
#pragma unroll
    for (int off = 16; off > 0; off >>= 1) s += __shfl_xor_sync(0xffffffffu, s, off);
    if (lane == 0) reds[wid] = s;
    __syncthreads();
    float tot = reds[0];
#pragma unroll
    for (int w = 1; w < 8; w++) tot += reds[w];
    float inv = 1.0f / tot;

    __half* oh = g_attn_h + row * (size_t)kHW;
    oh[tid] = __float2half_rn(e0 * inv);
    oh[tid + 256] = __float2half_rn(e1 * inv);
    if (tid < 64) oh[tid + 512] = __float2half_rn(e2 * inv);
}

// ---------------------------------------------------------------------------
// 6) Copy "cs" slice from vs_pe. dstSel<3: fp16 pair; dstSel==3: fp32 out.
// ---------------------------------------------------------------------------
__global__ __launch_bounds__(256) void copy_cs_kernel(int dstSel, float* outp,
                                                      int dstC, int t0) {
    int gid = blockIdx.x * 256 + threadIdx.x;
    const int total = kNB * kCP * kHW;
    if (gid >= total) return;
    int bz = gid / (kCP * kHW);
    int rem = gid % (kCP * kHW);
    int c = rem / kHW, pix = rem % kHW;
    int b = bz / kTp, t = bz % kTp;
    float v = g_vspe[((size_t)b * kT + t + t0) * kVCH * kHW + (size_t)(kSSTA + c) * kHW + pix];
    size_t di = (size_t)bz * dstC * kHW + (size_t)c * kHW + pix;
    if (dstSel == 3) {
        outp[di] = v;
    } else {
        __half hh = __float2half_rn(v);
        acc_b(dstSel)[di] = hh;
        acc_r(dstSel)[di] = __float2half_rn(v - __half2float(hh));
    }
}

// ---------------------------------------------------------------------------
// 7) Propagation GEMM: dst[bz,114+c,n] = sum_m A[bz,c,m]*attn[b,t0+t,n,m]
//    grid = (9 n-tiles(64), Mtiles(128), 144 bz). B operand = attn fp16.
// ---------------------------------------------------------------------------
__global__ __launch_bounds__(256) void prop_mma_kernel(int dstSel, float* outp, int srcSel,
                                                       int dstC, int Cin, int t0) {
    extern __shared__ __align__(16) char smem[];
    int bz = blockIdx.z;
    int b = bz / kTp, t = bz % kTp;
    int c0 = blockIdx.y * 128, n0 = blockIdx.x * 64;
    size_t abase = ((size_t)bz * Cin + c0) * kHW;
    size_t bbase = ((size_t)b * kTm1 + t0 + t) * kHW * kHW + (size_t)n0 * kHW;
    float acc[2][4][4];
    gemm_core(acc_b(srcSel) + abase, acc_r(srcSel) + abase, kHW,
              g_attn_h + bbase, kHW, kHW, acc, (Buf*)smem);

    int tid = threadIdx.x;
    int wid = tid >> 5, lane = tid & 31;
    int quad = lane >> 2, tq = lane & 3;
    int wm = wid & 3, wn = wid >> 2;
#pragma unroll
    for (int mi = 0; mi < 2; mi++)
#pragma unroll
        for (int rh = 0; rh < 2; rh++) {
            int rloc = wm * 32 + mi * 16 + quad + rh * 8;
            int cg = c0 + rloc;
            if (cg < Cin) {
                size_t di = ((size_t)bz * dstC + kCP + cg) * kHW + n0 + wn * 32 + tq * 2;
                if (dstSel == 3) {
#pragma unroll
                    for (int ni = 0; ni < 4; ni++) {
                        float2 v = make_float2(acc[mi][ni][rh * 2], acc[mi][ni][rh * 2 + 1]);
                        *(float2*)(outp + di + ni * 8) = v;
                    }
                } else {
                    __half* db = acc_b(dstSel);
                    __half* dr = acc_r(dstSel);
#pragma unroll
                    for (int ni = 0; ni < 4; ni++) {
                        uint32_t hw, rw;
                        split2h(acc[mi][ni][rh * 2], acc[mi][ni][rh * 2 + 1], hw, rw);
                        *(uint32_t*)(db + di + ni * 8) = hw;
                        *(uint32_t*)(dr + di + ni * 8) = rw;
                    }
                }
            }
        }
}

// ---------------------------------------------------------------------------
extern "C" void kernel_launch(void* const* d_in, const int* in_sizes, int n_in,
                              void* d_out, int out_size) {
    const float* x  = (const float*)d_in[0];
    const float* Wv = (const float*)d_in[1];
    const float* bv = (const float*)d_in[2];
    float* out = (float*)d_out;

    static bool attrs_set = false;
    if (!attrs_set) {
        cudaFuncSetAttribute(energy_mma_kernel,
                             cudaFuncAttributeMaxDynamicSharedMemorySize, kSmemDyn);
        cudaFuncSetAttribute(prop_mma_kernel,
                             cudaFuncAttributeMaxDynamicSharedMemorySize, kSmemDyn);
        attrs_set = true;
    }

    normalize_t_kernel<<<dim3(kBN * kT, kHW / 64), 256>>>(x);
    vproj_kernel<<<dim3(kHW / 64, kBN * kT), 256>>>(x, Wv, bv);
    pe_fill_kernel<<<(kBN * kT * 18 * kHW + 255) / 256, 256>>>();
    energy_mma_kernel<<<dim3(9, 5, kNAtt), 256, kSmemDyn>>>();
    softmax_kernel<<<kNAtt * kHW, 256>>>();
    const int copyG = (kNB * kCP * kHW + 255) / 256;
    copy_cs_kernel<<<copyG, 256>>>(0, out, kCP, 0);
    prop_mma_kernel<<<dim3(9, 1, kNB), 256, kSmemDyn>>>(1, out, 0, 2 * kCP, kCP, 0);
    copy_cs_kernel<<<copyG, 256>>>(1, out, 2 * kCP, 1);
    prop_mma_kernel<<<dim3(9, 2, kNB), 256, kSmemDyn>>>(2, out, 1, 3 * kCP, 2 * kCP, 1);
    copy_cs_kernel<<<copyG, 256>>>(2, out, 3 * kCP, 2);
    prop_mma_kernel<<<dim3(9, 3, kNB), 256, kSmemDyn>>>(3, out, 2, 4 * kCP, 3 * kCP, 2);
    copy_cs_kernel<<<copyG, 256>>>(3, out, 4 * kCP, 3);
}

// round 11
// speedup vs baseline: 2.2649x; 1.3438x over previous
#include <cuda_runtime.h>
#include <cuda_fp16.h>
#include <math.h>
#include <cstdint>

// ---------------------------------------------------------------------------
// Problem constants (fixed by setup_inputs)
// ---------------------------------------------------------------------------
namespace {
constexpr int kBN   = 16;
constexpr int kT    = 12;
constexpr int kCH   = 128;
constexpr int kH    = 24, kW = 24;
constexpr int kHW   = 576;
constexpr int kTm1  = 11;
constexpr int kTp   = 9;
constexpr int kNB   = 144;    // kBN * kTp
constexpr int kVCH  = 146;
constexpr int kSSTA = 32;
constexpr int kCP   = 114;
constexpr int kNAtt = 176;    // kBN * kTm1
constexpr float kScale = 0.0883883476483184f;  // 128^-0.5
constexpr int kLds  = 40;     // smem row stride in halves (80 B, conflict-free)
}

// ---------------------------------------------------------------------------
// Low-level helpers
// ---------------------------------------------------------------------------
__device__ __forceinline__ unsigned long long pack2(float lo, float hi) {
    unsigned long long r;
    asm("mov.b64 %0, {%1, %2};" : "=l"(r) : "f"(lo), "f"(hi));
    return r;
}
__device__ __forceinline__ unsigned long long dup2(float v) { return pack2(v, v); }
__device__ __forceinline__ void ffma2(unsigned long long& d, unsigned long long a,
                                      unsigned long long b) {
    asm("fma.rn.f32x2 %0, %1, %2, %3;" : "=l"(d) : "l"(a), "l"(b), "l"(d));
}
__device__ __forceinline__ void unpack2(unsigned long long v, float& lo, float& hi) {
    asm("mov.b64 {%0, %1}, %2;" : "=f"(lo), "=f"(hi) : "l"(v));
}

// fp16 MMA m16n8k16 (legacy HMMA path -- valid on non-'a' sm_103 target)
__device__ __forceinline__ void mma16816(float* c, const uint32_t* a, const uint32_t* b) {
    asm volatile(
        "mma.sync.aligned.m16n8k16.row.col.f32.f16.f16.f32 "
        "{%0,%1,%2,%3}, {%4,%5,%6,%7}, {%8,%9}, {%0,%1,%2,%3};"
        : "+f"(c[0]), "+f"(c[1]), "+f"(c[2]), "+f"(c[3])
        : "r"(a[0]), "r"(a[1]), "r"(a[2]), "r"(a[3]), "r"(b[0]), "r"(b[1]));
}

__device__ __forceinline__ uint32_t smem_u32p(const void* p) {
    uint32_t a;
    asm("{ .reg .u64 t; cvta.to.shared.u64 t, %1; cvt.u32.u64 %0, t; }"
        : "=r"(a) : "l"(p));
    return a;
}
__device__ __forceinline__ void ldm_x4(uint32_t* r, uint32_t saddr) {
    asm volatile("ldmatrix.sync.aligned.m8n8.x4.shared.b16 {%0,%1,%2,%3}, [%4];"
                 : "=r"(r[0]), "=r"(r[1]), "=r"(r[2]), "=r"(r[3]) : "r"(saddr));
}
__device__ __forceinline__ void cpasync16(void* sdst, const void* gsrc) {
    asm volatile("cp.async.ca.shared.global [%0], [%1], 16;"
                 :: "r"(smem_u32p(sdst)), "l"(gsrc));
}
__device__ __forceinline__ void cp_commit() {
    asm volatile("cp.async.commit_group;" ::: "memory");
}
__device__ __forceinline__ void cp_wait1() {
    asm volatile("cp.async.wait_group 1;" ::: "memory");
}
__device__ __forceinline__ void cp_wait0() {
    asm volatile("cp.async.wait_group 0;" ::: "memory");
}

// pack two fp16 from floats
__device__ __forceinline__ uint32_t h2pack(float x, float y) {
    __half hx = __float2half_rn(x), hy = __float2half_rn(y);
    return ((uint32_t)__half_as_ushort(hy) << 16) | __half_as_ushort(hx);
}

// ---------------------------------------------------------------------------
// Scratch (static device globals)
// ---------------------------------------------------------------------------
__device__ __half g_xT[((size_t)kBN * kT * kHW + 64) * kCH];
__device__ float g_attn[(size_t)kNAtt * kHW * kHW];     // energy out / softmax in
__device__ __half g_attn_h[((size_t)kNAtt * kHW + 64) * kHW];  // softmax out (fp16)
__device__ float g_vspe[kBN * kT * kVCH * kHW];
__device__ __half g_acc0[((size_t)kNB * kCP + 128) * kHW];
__device__ __half g_acc1[((size_t)kNB * 2 * kCP + 128) * kHW];
__device__ __half g_acc2[((size_t)kNB * 3 * kCP + 128) * kHW];

__device__ __forceinline__ __half* acc_buf(int s) {
    return s == 0 ? g_acc0 : (s == 1 ? g_acc1 : g_acc2);
}

// ---------------------------------------------------------------------------
// SMEM tile buffer (double-buffered).  128(m) x 64(n) CTA tile, pure fp16.
// pad[] caps occupancy at exactly 3 CTAs/SM (2*29184 = 58368 B): 4 CTAs
// lose to cross-CTA L1tex contention (measured R9 vs R10).
// ---------------------------------------------------------------------------
struct Buf {
    __half Ah[128 * kLds];   // 10240 B
    __half Bh[64 * kLds];    //  5120 B
    char pad[13824];
};
constexpr int kSmemDyn = 2 * sizeof(Buf);  // 58368 B -> exactly 3 CTAs/SM

__device__ __forceinline__ void stage_tile(
    Buf& d, const __half* __restrict__ Agh, int lda,
    const __half* __restrict__ Bgh, int ldb, int k0, int tid) {
#pragma unroll
    for (int s = 0; s < 3; s++) {
        int i = s * 256 + tid;  // 0..767
        int c = i & 3;
        int coff = c * 8;
        if (i < 512) {
            int row = i >> 2;
            cpasync16(&d.Ah[row * kLds + coff], Agh + (size_t)row * lda + k0 + coff);
        } else {
            int row = (i - 512) >> 2;
            cpasync16(&d.Bh[row * kLds + coff], Bgh + (size_t)row * ldb + k0 + coff);
        }
    }
}

// Core: C[128x64] accumulate over K (multiple of 32). 8 warps = 4(m) x 2(n),
// warp tile 32x32. Fragments via ldmatrix.x4; pure fp16 (1 MMA per frag set).
__device__ __forceinline__ void gemm_core(
    const __half* __restrict__ Agh, int lda,
    const __half* __restrict__ Bgh, int ldb,
    int K, float acc[2][4][4], Buf* bufs) {
    int tid = threadIdx.x;
    int wid = tid >> 5, lane = tid & 31;
    int wm = wid & 3, wn = wid >> 2;

    int j = lane >> 3, r = lane & 7;
    uint32_t aoff = (uint32_t)(((wm * 32 + ((j & 1) << 3) + r) * kLds + ((j >> 1) << 3)) * 2);
    uint32_t boff = (uint32_t)(((wn * 32 + ((j >> 1) << 3) + r) * kLds + ((j & 1) << 3)) * 2);

#pragma unroll
    for (int i = 0; i < 2; i++)
#pragma unroll
        for (int jj = 0; jj < 4; jj++)
#pragma unroll
            for (int q = 0; q < 4; q++) acc[i][jj][q] = 0.f;

    int nt = K / 32;
    stage_tile(bufs[0], Agh, lda, Bgh, ldb, 0, tid);
    cp_commit();
    for (int kt = 0; kt < nt; kt++) {
        if (kt + 1 < nt) {
            stage_tile(bufs[(kt + 1) & 1], Agh, lda, Bgh, ldb, (kt + 1) * 32, tid);
            cp_commit();
            cp_wait1();
        } else {
            cp_wait0();
        }
        __syncthreads();
        Buf& b = bufs[kt & 1];
        uint32_t Ah0 = smem_u32p(b.Ah) + aoff;
        uint32_t Bh0 = smem_u32p(b.Bh) + boff;
#pragma unroll
        for (int kb = 0; kb < 2; kb++) {
            uint32_t kbb = kb * 32;  // 16 halves = 32 bytes
            uint32_t ah[2][4];
            ldm_x4(ah[0], Ah0 + kbb);
            ldm_x4(ah[1], Ah0 + 16 * kLds * 2 + kbb);
            uint32_t bhf[4][2];
            {
                uint32_t t[4];
                ldm_x4(t, Bh0 + kbb);
                bhf[0][0] = t[0]; bhf[0][1] = t[1]; bhf[1][0] = t[2]; bhf[1][1] = t[3];
                ldm_x4(t, Bh0 + 16 * kLds * 2 + kbb);
                bhf[2][0] = t[0]; bhf[2][1] = t[1]; bhf[3][0] = t[2]; bhf[3][1] = t[3];
            }
#pragma unroll
            for (int mi = 0; mi < 2; mi++)
#pragma unroll
                for (int ni = 0; ni < 4; ni++)
                    mma16816(acc[mi][ni], ah[mi], bhf[ni]);
        }
        __syncthreads();
    }
}

// ---------------------------------------------------------------------------
// 1) Normalize + transpose + fp16 convert: g_xT[bt*HW+pix][c]
// ---------------------------------------------------------------------------
__global__ __launch_bounds__(256) void normalize_t_kernel(const float* __restrict__ x) {
    __shared__ float sm[128][65];
    __shared__ float psum[4][64];
    __shared__ float invs[64];
    int bt = blockIdx.x, p0 = blockIdx.y * 64;
    int tid = threadIdx.x;
    int px = tid & 63, cq = tid >> 6;
    const float* xb = x + (size_t)bt * kCH * kHW + p0;
    float s = 0.f;
#pragma unroll
    for (int j = 0; j < 32; j++) {
        int c = cq * 32 + j;
        float v = xb[(size_t)c * kHW + px];
        sm[c][px] = v;
        s += v * v;
    }
    psum[cq][px] = s;
    __syncthreads();
    if (tid < 64) {
        float tot = psum[0][tid] + psum[1][tid] + psum[2][tid] + psum[3][tid];
        invs[tid] = 1.0f / fmaxf(sqrtf(tot), 1e-12f);
    }
    __syncthreads();
    float iv = invs[px];
    size_t rb = ((size_t)bt * kHW + p0 + px) * kCH + cq * 32;
#pragma unroll
    for (int j4 = 0; j4 < 8; j4++) {
        int c = cq * 32 + j4 * 4;
        uint32_t w0 = h2pack(sm[c][px] * iv, sm[c + 1][px] * iv);
        uint32_t w1 = h2pack(sm[c + 2][px] * iv, sm[c + 3][px] * iv);
        *(uint2*)(g_xT + rb + j4 * 4) = make_uint2(w0, w1);
    }
}

// ---------------------------------------------------------------------------
// 2) Value projection (FFMA2 SIMT): vs_pe = Wv @ x + bv
// ---------------------------------------------------------------------------
__global__ __launch_bounds__(256) void vproj_kernel(const float* __restrict__ x,
                                                    const float* __restrict__ Wv,
                                                    const float* __restrict__ bv) {
    int bt = blockIdx.y;
    int p0 = blockIdx.x * 64;
    __shared__ __align__(16) float Ws[16][132];
    __shared__ __align__(16) float Xs[16][68];
    int tid = threadIdx.x;
    int ty = tid >> 4, tx = tid & 15;
    unsigned long long acc[4][4];
#pragma unroll
    for (int i = 0; i < 4; i++)
#pragma unroll
        for (int j = 0; j < 4; j++) acc[i][j] = 0ULL;

    const float* xb = x + (size_t)bt * kCH * kHW;
    for (int c0 = 0; c0 < kCH; c0 += 16) {
#pragma unroll
        for (int r = 0; r < 8; r++) {
            int lin = r * 256 + tid;
            int o = lin >> 4, c = lin & 15;
            Ws[c][o] = Wv[o * kCH + c0 + c];
        }
#pragma unroll
        for (int r = 0; r < 4; r++) {
            int lin = r * 256 + tid;
            int c = lin >> 6, j = lin & 63;
            Xs[c][j] = xb[(size_t)(c0 + c) * kHW + p0 + j];
        }
        __syncthreads();
#pragma unroll
        for (int c = 0; c < 16; c++) {
            float4 xv = *(const float4*)&Xs[c][tx * 4];
            float4 w0 = *(const float4*)&Ws[c][ty * 8];
            float4 w1 = *(const float4*)&Ws[c][ty * 8 + 4];
            unsigned long long wp[4] = {pack2(w0.x, w0.y), pack2(w0.z, w0.w),
                                        pack2(w1.x, w1.y), pack2(w1.z, w1.w)};
            unsigned long long xd[4] = {dup2(xv.x), dup2(xv.y), dup2(xv.z), dup2(xv.w)};
#pragma unroll
            for (int i = 0; i < 4; i++)
#pragma unroll
                for (int j = 0; j < 4; j++) ffma2(acc[i][j], wp[i], xd[j]);
        }
        __syncthreads();
    }
    float* ob = g_vspe + (size_t)bt * kVCH * kHW;
#pragma unroll
    for (int i = 0; i < 4; i++) {
        int o = ty * 8 + 2 * i;
        float b0 = bv[o], b1 = bv[o + 1];
#pragma unroll
        for (int j = 0; j < 4; j++) {
            float lo, hi;
            unpack2(acc[i][j], lo, hi);
            ob[(size_t)o * kHW + p0 + tx * 4 + j] = lo + b0;
            ob[(size_t)(o + 1) * kHW + p0 + tx * 4 + j] = hi + b1;
        }
    }
}

// ---------------------------------------------------------------------------
// 3) Positional-encoding channels 128..145 of vs_pe
// ---------------------------------------------------------------------------
__global__ __launch_bounds__(256) void pe_fill_kernel() {
    int gid = blockIdx.x * 256 + threadIdx.x;
    const int total = kBN * kT * 18 * kHW;
    if (gid >= total) return;
    int bt  = gid / (18 * kHW);
    int rem = gid % (18 * kHW);
    int c = rem / kHW, pix = rem % kHW;
    int yy = pix / kW, xx = pix % kW;
    float yc = -1.0f + 2.0f * (float)yy / (float)(kH - 1);
    float xc = -1.0f + 2.0f * (float)xx / (float)(kW - 1);
    float val;
    if (c == 0) val = yc;
    else if (c == 1) val = xc;
    else {
        int i = (c - 2) >> 2;
        int k = (c - 2) & 3;
        float coord = (k & 1) ? xc : yc;
        float f = (float)(1 << i) * 3.14159265358979323846f * coord;
        val = (k < 2) ? sinf(f) : cosf(f);
    }
    g_vspe[(size_t)bt * kVCH * kHW + (size_t)(kCH + c) * kHW + pix] = val;
}

// ---------------------------------------------------------------------------
// 4) Energy GEMM: e[g,n,m] = scale * sum_c qT[n,c]*kT[m,c]; out fp32.
//    grid = (9 m-tiles(64), 5 n-tiles(128), 176 g)
// ---------------------------------------------------------------------------
__global__ __launch_bounds__(256) void energy_mma_kernel() {
    extern __shared__ __align__(16) char smem[];
    int g = blockIdx.z;
    int b = g / kTm1, t = g % kTm1;
    int m0 = blockIdx.y * 128, n0 = blockIdx.x * 64;
    size_t abase = ((size_t)(b * kT + t + 1) * kHW + m0) * kCH;
    size_t bbase = ((size_t)(b * kT + t) * kHW + n0) * kCH;
    float acc[2][4][4];
    gemm_core(g_xT + abase, kCH, g_xT + bbase, kCH, kCH, acc, (Buf*)smem);

    int tid = threadIdx.x;
    int wid = tid >> 5, lane = tid & 31;
    int quad = lane >> 2, tq = lane & 3;
    int wm = wid & 3, wn = wid >> 2;
    int mvalid = kHW - m0;
    float* C = g_attn + (size_t)g * kHW * kHW + (size_t)m0 * kHW + n0;
#pragma unroll
    for (int mi = 0; mi < 2; mi++)
#pragma unroll
        for (int rh = 0; rh < 2; rh++) {
            int rrow = wm * 32 + mi * 16 + quad + rh * 8;
            if (rrow < mvalid) {
#pragma unroll
                for (int ni = 0; ni < 4; ni++) {
                    float2 v = make_float2(acc[mi][ni][rh * 2] * kScale,
                                           acc[mi][ni][rh * 2 + 1] * kScale);
                    *(float2*)(C + (size_t)rrow * kHW + wn * 32 + ni * 8 + tq * 2) = v;
                }
            }
        }
}

// ---------------------------------------------------------------------------
// 5) Softmax row-wise; writes single fp16 attn
// ---------------------------------------------------------------------------
__global__ __launch_bounds__(256) void softmax_kernel() {
    size_t row = blockIdx.x;
    const float* p = g_attn + row * (size_t)kHW;
    int tid = threadIdx.x;
    int lane = tid & 31, wid = tid >> 5;
    __shared__ float redm[8], reds[8];

    float a = p[tid];
    float b = p[tid + 256];
    float c = (tid < 64) ? p[tid + 512] : -3.0e38f;
    float m = fmaxf(fmaxf(a, b), c);
#pragma unroll
    for (int off = 16; off > 0; off >>= 1) m = fmaxf(m, __shfl_xor_sync(0xffffffffu, m, off));
    if (lane == 0) redm[wid] = m;
    __syncthreads();
    float bm = redm[0];
#pragma unroll
    for (int w = 1; w < 8; w++) bm = fmaxf(bm, redm[w]);

    float e0 = expf(a - bm);
    float e1 = expf(b - bm);
    float e2 = (tid < 64) ? expf(c - bm) : 0.f;
    float s = e0 + e1 + e2;
#pragma unroll
    for (int off = 16; off > 0; off >>= 1) s += __shfl_xor_sync(0xffffffffu, s, off);
    if (lane == 0) reds[wid] = s;
    __syncthreads();
    float tot = reds[0];
#pragma unroll
    for (int w = 1; w < 8; w++) tot += reds[w];
    float inv = 1.0f / tot;

    __half* oh = g_attn_h + row * (size_t)kHW;
    oh[tid] = __float2half_rn(e0 * inv);
    oh[tid + 256] = __float2half_rn(e1 * inv);
    if (tid < 64) oh[tid + 512] = __float2half_rn(e2 * inv);
}

// ---------------------------------------------------------------------------
// 6) Copy "cs" slice from vs_pe. dstSel<3: fp16; dstSel==3: fp32 out.
// ---------------------------------------------------------------------------
__global__ __launch_bounds__(256) void copy_cs_kernel(int dstSel, float* outp,
                                                      int dstC, int t0) {
    int gid = blockIdx.x * 256 + threadIdx.x;
    const int total = kNB * kCP * kHW;
    if (gid >= total) return;
    int bz = gid / (kCP * kHW);
    int rem = gid % (kCP * kHW);
    int c = rem / kHW, pix = rem % kHW;
    int b = bz / kTp, t = bz % kTp;
    float v = g_vspe[((size_t)b * kT + t + t0) * kVCH * kHW + (size_t)(kSSTA + c) * kHW + pix];
    size_t di = (size_t)bz * dstC * kHW + (size_t)c * kHW + pix;
    if (dstSel == 3) {
        outp[di] = v;
    } else {
        acc_buf(dstSel)[di] = __float2half_rn(v);
    }
}

// ---------------------------------------------------------------------------
// 7) Propagation GEMM: dst[bz,114+c,n] = sum_m A[bz,c,m]*attn[b,t0+t,n,m]
//    grid = (9 n-tiles(64), Mtiles(128), 144 bz).
// ---------------------------------------------------------------------------
__global__ __launch_bounds__(256) void prop_mma_kernel(int dstSel, float* outp, int srcSel,
                                                       int dstC, int Cin, int t0) {
    extern __shared__ __align__(16) char smem[];
    int bz = blockIdx.z;
    int b = bz / kTp, t = bz % kTp;
    int c0 = blockIdx.y * 128, n0 = blockIdx.x * 64;
    size_t abase = ((size_t)bz * Cin + c0) * kHW;
    size_t bbase = ((size_t)b * kTm1 + t0 + t) * kHW * kHW + (size_t)n0 * kHW;
    float acc[2][4][4];
    gemm_core(acc_buf(srcSel) + abase, kHW, g_attn_h + bbase, kHW, kHW, acc, (Buf*)smem);

    int tid = threadIdx.x;
    int wid = tid >> 5, lane = tid & 31;
    int quad = lane >> 2, tq = lane & 3;
    int wm = wid & 3, wn = wid >> 2;
#pragma unroll
    for (int mi = 0; mi < 2; mi++)
#pragma unroll
        for (int rh = 0; rh < 2; rh++) {
            int rloc = wm * 32 + mi * 16 + quad + rh * 8;
            int cg = c0 + rloc;
            if (cg < Cin) {
                size_t di = ((size_t)bz * dstC + kCP + cg) * kHW + n0 + wn * 32 + tq * 2;
                if (dstSel == 3) {
#pragma unroll
                    for (int ni = 0; ni < 4; ni++) {
                        float2 v = make_float2(acc[mi][ni][rh * 2], acc[mi][ni][rh * 2 + 1]);
                        *(float2*)(outp + di + ni * 8) = v;
                    }
                } else {
                    __half* db = acc_buf(dstSel);
#pragma unroll
                    for (int ni = 0; ni < 4; ni++) {
                        uint32_t hw = h2pack(acc[mi][ni][rh * 2], acc[mi][ni][rh * 2 + 1]);
                        *(uint32_t*)(db + di + ni * 8) = hw;
                    }
                }
            }
        }
}

// ---------------------------------------------------------------------------
extern "C" void kernel_launch(void* const* d_in, const int* in_sizes, int n_in,
                              void* d_out, int out_size) {
    const float* x  = (const float*)d_in[0];
    const float* Wv = (const float*)d_in[1];
    const float* bv = (const float*)d_in[2];
    float* out = (float*)d_out;

    static bool attrs_set = false;
    if (!attrs_set) {
        cudaFuncSetAttribute(energy_mma_kernel,
                             cudaFuncAttributeMaxDynamicSharedMemorySize, kSmemDyn);
        cudaFuncSetAttribute(prop_mma_kernel,
                             cudaFuncAttributeMaxDynamicSharedMemorySize, kSmemDyn);
        attrs_set = true;
    }

    normalize_t_kernel<<<dim3(kBN * kT, kHW / 64), 256>>>(x);
    vproj_kernel<<<dim3(kHW / 64, kBN * kT), 256>>>(x, Wv, bv);
    pe_fill_kernel<<<(kBN * kT * 18 * kHW + 255) / 256, 256>>>();
    energy_mma_kernel<<<dim3(9, 5, kNAtt), 256, kSmemDyn>>>();
    softmax_kernel<<<kNAtt * kHW, 256>>>();
    const int copyG = (kNB * kCP * kHW + 255) / 256;
    copy_cs_kernel<<<copyG, 256>>>(0, out, kCP, 0);
    prop_mma_kernel<<<dim3(9, 1, kNB), 256, kSmemDyn>>>(1, out, 0, 2 * kCP, kCP, 0);
    copy_cs_kernel<<<copyG, 256>>>(1, out, 2 * kCP, 1);
    prop_mma_kernel<<<dim3(9, 2, kNB), 256, kSmemDyn>>>(2, out, 1, 3 * kCP, 2 * kCP, 1);
    copy_cs_kernel<<<copyG, 256>>>(2, out, 3 * kCP, 2);
    prop_mma_kernel<<<dim3(9, 3, kNB), 256, kSmemDyn>>>(3, out, 2, 4 * kCP, 3 * kCP, 2);
    copy_cs_kernel<<<copyG, 256>>>(3, out, 4 * kCP, 3);
}

// round 12
// speedup vs baseline: 2.4336x; 1.0745x over previous
#include <cuda_runtime.h>
#include <cuda_fp16.h>
#include <math.h>
#include <cstdint>

// ---------------------------------------------------------------------------
// Problem constants (fixed by setup_inputs)
// ---------------------------------------------------------------------------
namespace {
constexpr int kBN   = 16;
constexpr int kT    = 12;
constexpr int kCH   = 128;
constexpr int kH    = 24, kW = 24;
constexpr int kHW   = 576;
constexpr int kTm1  = 11;
constexpr int kTp   = 9;
constexpr int kNB   = 144;    // kBN * kTp
constexpr int kVCH  = 146;
constexpr int kSSTA = 32;
constexpr int kCP   = 114;
constexpr int kNAtt = 176;    // kBN * kTm1
constexpr float kScale = 0.0883883476483184f;  // 128^-0.5
constexpr int kLds  = 40;     // smem row stride in halves (80 B, conflict-free)
}

// ---------------------------------------------------------------------------
// Low-level helpers
// ---------------------------------------------------------------------------
__device__ __forceinline__ unsigned long long pack2(float lo, float hi) {
    unsigned long long r;
    asm("mov.b64 %0, {%1, %2};" : "=l"(r) : "f"(lo), "f"(hi));
    return r;
}
__device__ __forceinline__ unsigned long long dup2(float v) { return pack2(v, v); }
__device__ __forceinline__ void ffma2(unsigned long long& d, unsigned long long a,
                                      unsigned long long b) {
    asm("fma.rn.f32x2 %0, %1, %2, %3;" : "=l"(d) : "l"(a), "l"(b), "l"(d));
}
__device__ __forceinline__ void unpack2(unsigned long long v, float& lo, float& hi) {
    asm("mov.b64 {%0, %1}, %2;" : "=f"(lo), "=f"(hi) : "l"(v));
}

// fp16 MMA m16n8k16 (legacy HMMA path -- valid on non-'a' sm_103 target)
__device__ __forceinline__ void mma16816(float* c, const uint32_t* a, const uint32_t* b) {
    asm volatile(
        "mma.sync.aligned.m16n8k16.row.col.f32.f16.f16.f32 "
        "{%0,%1,%2,%3}, {%4,%5,%6,%7}, {%8,%9}, {%0,%1,%2,%3};"
        : "+f"(c[0]), "+f"(c[1]), "+f"(c[2]), "+f"(c[3])
        : "r"(a[0]), "r"(a[1]), "r"(a[2]), "r"(a[3]), "r"(b[0]), "r"(b[1]));
}

__device__ __forceinline__ uint32_t smem_u32p(const void* p) {
    uint32_t a;
    asm("{ .reg .u64 t; cvta.to.shared.u64 t, %1; cvt.u32.u64 %0, t; }"
        : "=r"(a) : "l"(p));
    return a;
}
__device__ __forceinline__ void ldm_x4(uint32_t* r, uint32_t saddr) {
    asm volatile("ldmatrix.sync.aligned.m8n8.x4.shared.b16 {%0,%1,%2,%3}, [%4];"
                 : "=r"(r[0]), "=r"(r[1]), "=r"(r[2]), "=r"(r[3]) : "r"(saddr));
}
__device__ __forceinline__ void cpasync16(void* sdst, const void* gsrc) {
    asm volatile("cp.async.ca.shared.global [%0], [%1], 16;"
                 :: "r"(smem_u32p(sdst)), "l"(gsrc));
}
__device__ __forceinline__ void cp_commit() {
    asm volatile("cp.async.commit_group;" ::: "memory");
}
__device__ __forceinline__ void cp_wait1() {
    asm volatile("cp.async.wait_group 1;" ::: "memory");
}
__device__ __forceinline__ void cp_wait0() {
    asm volatile("cp.async.wait_group 0;" ::: "memory");
}

// pack two fp16 from floats
__device__ __forceinline__ uint32_t h2pack(float x, float y) {
    __half hx = __float2half_rn(x), hy = __float2half_rn(y);
    return ((uint32_t)__half_as_ushort(hy) << 16) | __half_as_ushort(hx);
}

// ---------------------------------------------------------------------------
// Scratch (static device globals)
// ---------------------------------------------------------------------------
__device__ __half g_xT[((size_t)kBN * kT * kHW + 64) * kCH];
// fp16 logits written by energy; softmax converts IN PLACE to attn probs.
__device__ __half g_attn_h[((size_t)kNAtt * kHW + 64) * kHW];
__device__ float g_vspe[kBN * kT * kVCH * kHW];
__device__ __half g_acc0[((size_t)kNB * kCP + 128) * kHW];
__device__ __half g_acc1[((size_t)kNB * 2 * kCP + 128) * kHW];
__device__ __half g_acc2[((size_t)kNB * 3 * kCP + 128) * kHW];

__device__ __forceinline__ __half* acc_buf(int s) {
    return s == 0 ? g_acc0 : (s == 1 ? g_acc1 : g_acc2);
}

// ---------------------------------------------------------------------------
// SMEM tile buffer (double-buffered).  128(m) x 128(n) CTA tile, pure fp16.
// pad[] keeps per-CTA dynamic smem at 29184*2 = 58368 B so at most 3 CTAs/SM
// fit (>=4 CTAs lose to cross-CTA L1tex contention, measured R9 vs R10);
// register use (~105/thread) will typically cap it at 2 CTAs.
// ---------------------------------------------------------------------------
struct Buf {
    __half Ah[128 * kLds];   // 10240 B
    __half Bh[128 * kLds];   // 10240 B
    char pad[8704];
};
constexpr int kSmemDyn = 2 * sizeof(Buf);  // 58368 B

__device__ __forceinline__ void stage_tile(
    Buf& d, const __half* __restrict__ Agh, int lda,
    const __half* __restrict__ Bgh, int ldb, int k0, int tid) {
#pragma unroll
    for (int s = 0; s < 4; s++) {
        int i = s * 256 + tid;  // 0..1023
        int row = (i >> 2) & 127, c = i & 3;
        int coff = c * 8;
        if (i < 512)
            cpasync16(&d.Ah[row * kLds + coff], Agh + (size_t)row * lda + k0 + coff);
        else
            cpasync16(&d.Bh[row * kLds + coff], Bgh + (size_t)row * ldb + k0 + coff);
    }
}

// Core: C[128x128] accumulate over K (multiple of 32). 8 warps = 4(m) x 2(n),
// warp tile 32(m) x 64(n). Fragments via ldmatrix.x4; pure fp16.
__device__ __forceinline__ void gemm_core(
    const __half* __restrict__ Agh, int lda,
    const __half* __restrict__ Bgh, int ldb,
    int K, float acc[2][8][4], Buf* bufs) {
    int tid = threadIdx.x;
    int wid = tid >> 5, lane = tid & 31;
    int wm = wid & 3, wn = wid >> 2;

    int j = lane >> 3, r = lane & 7;
    uint32_t aoff = (uint32_t)(((wm * 32 + ((j & 1) << 3) + r) * kLds + ((j >> 1) << 3)) * 2);
    uint32_t boff = (uint32_t)(((wn * 64 + ((j >> 1) << 3) + r) * kLds + ((j & 1) << 3)) * 2);

#pragma unroll
    for (int i = 0; i < 2; i++)
#pragma unroll
        for (int jj = 0; jj < 8; jj++)
#pragma unroll
            for (int q = 0; q < 4; q++) acc[i][jj][q] = 0.f;

    int nt = K / 32;
    stage_tile(bufs[0], Agh, lda, Bgh, ldb, 0, tid);
    cp_commit();
    for (int kt = 0; kt < nt; kt++) {
        if (kt + 1 < nt) {
            stage_tile(bufs[(kt + 1) & 1], Agh, lda, Bgh, ldb, (kt + 1) * 32, tid);
            cp_commit();
            cp_wait1();
        } else {
            cp_wait0();
        }
        __syncthreads();
        Buf& b = bufs[kt & 1];
        uint32_t Ah0 = smem_u32p(b.Ah) + aoff;
        uint32_t Bh0 = smem_u32p(b.Bh) + boff;
#pragma unroll
        for (int kb = 0; kb < 2; kb++) {
            uint32_t kbb = kb * 32;  // 16 halves = 32 bytes
            uint32_t ah[2][4];
            ldm_x4(ah[0], Ah0 + kbb);
            ldm_x4(ah[1], Ah0 + 16 * kLds * 2 + kbb);
#pragma unroll
            for (int half = 0; half < 2; half++) {
                uint32_t roff = (uint32_t)(half * 32 * kLds * 2) + kbb;
                uint32_t bhf[4][2];
                {
                    uint32_t t[4];
                    ldm_x4(t, Bh0 + roff);
                    bhf[0][0] = t[0]; bhf[0][1] = t[1]; bhf[1][0] = t[2]; bhf[1][1] = t[3];
                    ldm_x4(t, Bh0 + roff + 16 * kLds * 2);
                    bhf[2][0] = t[0]; bhf[2][1] = t[1]; bhf[3][0] = t[2]; bhf[3][1] = t[3];
                }
#pragma unroll
                for (int mi = 0; mi < 2; mi++)
#pragma unroll
                    for (int ni = 0; ni < 4; ni++)
                        mma16816(acc[mi][half * 4 + ni], ah[mi], bhf[ni]);
            }
        }
        __syncthreads();
    }
}

// ---------------------------------------------------------------------------
// 1) Normalize + transpose + fp16 convert: g_xT[bt*HW+pix][c]
// ---------------------------------------------------------------------------
__global__ __launch_bounds__(256) void normalize_t_kernel(const float* __restrict__ x) {
    __shared__ float sm[128][65];
    __shared__ float psum[4][64];
    __shared__ float invs[64];
    int bt = blockIdx.x, p0 = blockIdx.y * 64;
    int tid = threadIdx.x;
    int px = tid & 63, cq = tid >> 6;
    const float* xb = x + (size_t)bt * kCH * kHW + p0;
    float s = 0.f;
#pragma unroll
    for (int j = 0; j < 32; j++) {
        int c = cq * 32 + j;
        float v = xb[(size_t)c * kHW + px];
        sm[c][px] = v;
        s += v * v;
    }
    psum[cq][px] = s;
    __syncthreads();
    if (tid < 64) {
        float tot = psum[0][tid] + psum[1][tid] + psum[2][tid] + psum[3][tid];
        invs[tid] = 1.0f / fmaxf(sqrtf(tot), 1e-12f);
    }
    __syncthreads();
    float iv = invs[px];
    size_t rb = ((size_t)bt * kHW + p0 + px) * kCH + cq * 32;
#pragma unroll
    for (int j4 = 0; j4 < 8; j4++) {
        int c = cq * 32 + j4 * 4;
        uint32_t w0 = h2pack(sm[c][px] * iv, sm[c + 1][px] * iv);
        uint32_t w1 = h2pack(sm[c + 2][px] * iv, sm[c + 3][px] * iv);
        *(uint2*)(g_xT + rb + j4 * 4) = make_uint2(w0, w1);
    }
}

// ---------------------------------------------------------------------------
// 2) Value projection (FFMA2 SIMT): vs_pe = Wv @ x + bv
// ---------------------------------------------------------------------------
__global__ __launch_bounds__(256) void vproj_kernel(const float* __restrict__ x,
                                                    const float* __restrict__ Wv,
                                                    const float* __restrict__ bv) {
    int bt = blockIdx.y;
    int p0 = blockIdx.x * 64;
    __shared__ __align__(16) float Ws[16][132];
    __shared__ __align__(16) float Xs[16][68];
    int tid = threadIdx.x;
    int ty = tid >> 4, tx = tid & 15;
    unsigned long long acc[4][4];
#pragma unroll
    for (int i = 0; i < 4; i++)
#pragma unroll
        for (int j = 0; j < 4; j++) acc[i][j] = 0ULL;

    const float* xb = x + (size_t)bt * kCH * kHW;
    for (int c0 = 0; c0 < kCH; c0 += 16) {
#pragma unroll
        for (int r = 0; r < 8; r++) {
            int lin = r * 256 + tid;
            int o = lin >> 4, c = lin & 15;
            Ws[c][o] = Wv[o * kCH + c0 + c];
        }
#pragma unroll
        for (int r = 0; r < 4; r++) {
            int lin = r * 256 + tid;
            int c = lin >> 6, j = lin & 63;
            Xs[c][j] = xb[(size_t)(c0 + c) * kHW + p0 + j];
        }
        __syncthreads();
#pragma unroll
        for (int c = 0; c < 16; c++) {
            float4 xv = *(const float4*)&Xs[c][tx * 4];
            float4 w0 = *(const float4*)&Ws[c][ty * 8];
            float4 w1 = *(const float4*)&Ws[c][ty * 8 + 4];
            unsigned long long wp[4] = {pack2(w0.x, w0.y), pack2(w0.z, w0.w),
                                        pack2(w1.x, w1.y), pack2(w1.z, w1.w)};
            unsigned long long xd[4] = {dup2(xv.x), dup2(xv.y), dup2(xv.z), dup2(xv.w)};
#pragma unroll
            for (int i = 0; i < 4; i++)
#pragma unroll
                for (int j = 0; j < 4; j++) ffma2(acc[i][j], wp[i], xd[j]);
        }
        __syncthreads();
    }
    float* ob = g_vspe + (size_t)bt * kVCH * kHW;
#pragma unroll
    for (int i = 0; i < 4; i++) {
        int o = ty * 8 + 2 * i;
        float b0 = bv[o], b1 = bv[o + 1];
#pragma unroll
        for (int j = 0; j < 4; j++) {
            float lo, hi;
            unpack2(acc[i][j], lo, hi);
            ob[(size_t)o * kHW + p0 + tx * 4 + j] = lo + b0;
            ob[(size_t)(o + 1) * kHW + p0 + tx * 4 + j] = hi + b1;
        }
    }
}

// ---------------------------------------------------------------------------
// 3) Positional-encoding channels 128..145 of vs_pe
// ---------------------------------------------------------------------------
__global__ __launch_bounds__(256) void pe_fill_kernel() {
    int gid = blockIdx.x * 256 + threadIdx.x;
    const int total = kBN * kT * 18 * kHW;
    if (gid >= total) return;
    int bt  = gid / (18 * kHW);
    int rem = gid % (18 * kHW);
    int c = rem / kHW, pix = rem % kHW;
    int yy = pix / kW, xx = pix % kW;
    float yc = -1.0f + 2.0f * (float)yy / (float)(kH - 1);
    float xc = -1.0f + 2.0f * (float)xx / (float)(kW - 1);
    float val;
    if (c == 0) val = yc;
    else if (c == 1) val = xc;
    else {
        int i = (c - 2) >> 2;
        int k = (c - 2) & 3;
        float coord = (k & 1) ? xc : yc;
        float f = (float)(1 << i) * 3.14159265358979323846f * coord;
        val = (k < 2) ? sinf(f) : cosf(f);
    }
    g_vspe[(size_t)bt * kVCH * kHW + (size_t)(kCH + c) * kHW + pix] = val;
}

// ---------------------------------------------------------------------------
// 4) Energy GEMM: logits[g,n,m] = scale * sum_c qT[n,c]*kT[m,c]; out fp16.
//    grid = (5 m-tiles(128), 5 n-tiles(128), 176 g)
// ---------------------------------------------------------------------------
__global__ __launch_bounds__(256) void energy_mma_kernel() {
    extern __shared__ __align__(16) char smem[];
    int g = blockIdx.z;
    int b = g / kTm1, t = g % kTm1;
    int m0 = blockIdx.y * 128, n0 = blockIdx.x * 128;
    size_t abase = ((size_t)(b * kT + t + 1) * kHW + m0) * kCH;
    size_t bbase = ((size_t)(b * kT + t) * kHW + n0) * kCH;
    float acc[2][8][4];
    gemm_core(g_xT + abase, kCH, g_xT + bbase, kCH, kCH, acc, (Buf*)smem);

    int tid = threadIdx.x;
    int wid = tid >> 5, lane = tid & 31;
    int quad = lane >> 2, tq = lane & 3;
    int wm = wid & 3, wn = wid >> 2;
    int mvalid = kHW - m0;
    __half* C = g_attn_h + (size_t)g * kHW * kHW + (size_t)m0 * kHW;
#pragma unroll
    for (int mi = 0; mi < 2; mi++)
#pragma unroll
        for (int rh = 0; rh < 2; rh++) {
            int rrow = wm * 32 + mi * 16 + quad + rh * 8;
            if (rrow < mvalid) {
#pragma unroll
                for (int ni = 0; ni < 8; ni++) {
                    int ncol = n0 + wn * 64 + ni * 8 + tq * 2;
                    if (ncol < kHW) {
                        uint32_t hw = h2pack(acc[mi][ni][rh * 2] * kScale,
                                             acc[mi][ni][rh * 2 + 1] * kScale);
                        *(uint32_t*)(C + (size_t)rrow * kHW + ncol) = hw;
                    }
                }
            }
        }
}

// ---------------------------------------------------------------------------
// 5) Softmax row-wise, IN PLACE on fp16 logits -> fp16 probabilities
// ---------------------------------------------------------------------------
__global__ __launch_bounds__(256) void softmax_kernel() {
    size_t row = blockIdx.x;
    __half* p = g_attn_h + row * (size_t)kHW;
    int tid = threadIdx.x;
    int lane = tid & 31, wid = tid >> 5;
    __shared__ float redm[8], reds[8];

    float a = __half2float(p[tid]);
    float b = __half2float(p[tid + 256]);
    float c = (tid < 64) ? __half2float(p[tid + 512]) : -3.0e38f;
    float m = fmaxf(fmaxf(a, b), c);
#pragma unroll
    for (int off = 16; off > 0; off >>= 1) m = fmaxf(m, __shfl_xor_sync(0xffffffffu, m, off));
    if (lane == 0) redm[wid] = m;
    __syncthreads();
    float bm = redm[0];
#pragma unroll
    for (int w = 1; w < 8; w++) bm = fmaxf(bm, redm[w]);

    float e0 = expf(a - bm);
    float e1 = expf(b - bm);
    float e2 = (tid < 64) ? expf(c - bm) : 0.f;
    float s = e0 + e1 + e2;
#pragma unroll
    for (int off = 16; off > 0; off >>= 1) s += __shfl_xor_sync(0xffffffffu, s, off);
    if (lane == 0) reds[wid] = s;
    __syncthreads();
    float tot = reds[0];
#pragma unroll
    for (int w = 1; w < 8; w++) tot += reds[w];
    float inv = 1.0f / tot;

    __syncthreads();  // all reads done before in-place writes
    p[tid] = __float2half_rn(e0 * inv);
    p[tid + 256] = __float2half_rn(e1 * inv);
    if (tid < 64) p[tid + 512] = __float2half_rn(e2 * inv);
}

// ---------------------------------------------------------------------------
// 6) Copy "cs" slice from vs_pe. dstSel<3: fp16; dstSel==3: fp32 out.
// ---------------------------------------------------------------------------
__global__ __launch_bounds__(256) void copy_cs_kernel(int dstSel, float* outp,
                                                      int dstC, int t0) {
    int gid = blockIdx.x * 256 + threadIdx.x;
    const int total = kNB * kCP * kHW;
    if (gid >= total) return;
    int bz = gid / (kCP * kHW);
    int rem = gid % (kCP * kHW);
    int c = rem / kHW, pix = rem % kHW;
    int b = bz / kTp, t = bz % kTp;
    float v = g_vspe[((size_t)b * kT + t + t0) * kVCH * kHW + (size_t)(kSSTA + c) * kHW + pix];
    size_t di = (size_t)bz * dstC * kHW + (size_t)c * kHW + pix;
    if (dstSel == 3) {
        outp[di] = v;
    } else {
        acc_buf(dstSel)[di] = __float2half_rn(v);
    }
}

// ---------------------------------------------------------------------------
// 7) Propagation GEMM: dst[bz,114+c,n] = sum_m A[bz,c,m]*attn[b,t0+t,n,m]
//    grid = (5 n-tiles(128), Mtiles(128), 144 bz).
// ---------------------------------------------------------------------------
__global__ __launch_bounds__(256) void prop_mma_kernel(int dstSel, float* outp, int srcSel,
                                                       int dstC, int Cin, int t0) {
    extern __shared__ __align__(16) char smem[];
    int bz = blockIdx.z;
    int b = bz / kTp, t = bz % kTp;
    int c0 = blockIdx.y * 128, n0 = blockIdx.x * 128;
    size_t abase = ((size_t)bz * Cin + c0) * kHW;
    size_t bbase = ((size_t)b * kTm1 + t0 + t) * kHW * kHW + (size_t)n0 * kHW;
    float acc[2][8][4];
    gemm_core(acc_buf(srcSel) + abase, kHW, g_attn_h + bbase, kHW, kHW, acc, (Buf*)smem);

    int tid = threadIdx.x;
    int wid = tid >> 5, lane = tid & 31;
    int quad = lane >> 2, tq = lane & 3;
    int wm = wid & 3, wn = wid >> 2;
#pragma unroll
    for (int mi = 0; mi < 2; mi++)
#pragma unroll
        for (int rh = 0; rh < 2; rh++) {
            int rloc = wm * 32 + mi * 16 + quad + rh * 8;
            int cg = c0 + rloc;
            if (cg < Cin) {
                size_t rbase = ((size_t)bz * dstC + kCP + cg) * kHW;
#pragma unroll
                for (int ni = 0; ni < 8; ni++) {
                    int ncol = n0 + wn * 64 + ni * 8 + tq * 2;
                    if (ncol < kHW) {
                        if (dstSel == 3) {
                            float2 v = make_float2(acc[mi][ni][rh * 2],
                                                   acc[mi][ni][rh * 2 + 1]);
                            *(float2*)(outp + rbase + ncol) = v;
                        } else {
                            uint32_t hw = h2pack(acc[mi][ni][rh * 2],
                                                 acc[mi][ni][rh * 2 + 1]);
                            *(uint32_t*)(acc_buf(dstSel) + rbase + ncol) = hw;
                        }
                    }
                }
            }
        }
}

// ---------------------------------------------------------------------------
extern "C" void kernel_launch(void* const* d_in, const int* in_sizes, int n_in,
                              void* d_out, int out_size) {
    const float* x  = (const float*)d_in[0];
    const float* Wv = (const float*)d_in[1];
    const float* bv = (const float*)d_in[2];
    float* out = (float*)d_out;

    static bool attrs_set = false;
    if (!attrs_set) {
        cudaFuncSetAttribute(energy_mma_kernel,
                             cudaFuncAttributeMaxDynamicSharedMemorySize, kSmemDyn);
        cudaFuncSetAttribute(prop_mma_kernel,
                             cudaFuncAttributeMaxDynamicSharedMemorySize, kSmemDyn);
        attrs_set = true;
    }

    normalize_t_kernel<<<dim3(kBN * kT, kHW / 64), 256>>>(x);
    vproj_kernel<<<dim3(kHW / 64, kBN * kT), 256>>>(x, Wv, bv);
    pe_fill_kernel<<<(kBN * kT * 18 * kHW + 255) / 256, 256>>>();
    energy_mma_kernel<<<dim3(5, 5, kNAtt), 256, kSmemDyn>>>();
    softmax_kernel<<<kNAtt * kHW, 256>>>();
    const int copyG = (kNB * kCP * kHW + 255) / 256;
    copy_cs_kernel<<<copyG, 256>>>(0, out, kCP, 0);
    prop_mma_kernel<<<dim3(5, 1, kNB), 256, kSmemDyn>>>(1, out, 0, 2 * kCP, kCP, 0);
    copy_cs_kernel<<<copyG, 256>>>(1, out, 2 * kCP, 1);
    prop_mma_kernel<<<dim3(5, 2, kNB), 256, kSmemDyn>>>(2, out, 1, 3 * kCP, 2 * kCP, 1);
    copy_cs_kernel<<<copyG, 256>>>(2, out, 3 * kCP, 2);
    prop_mma_kernel<<<dim3(5, 3, kNB), 256, kSmemDyn>>>(3, out, 2, 4 * kCP, 3 * kCP, 2);
    copy_cs_kernel<<<copyG, 256>>>(3, out, 4 * kCP, 3);
}

// round 13
// speedup vs baseline: 2.6103x; 1.0726x over previous
#include <cuda_runtime.h>
#include <cuda_fp16.h>
#include <math.h>
#include <cstdint>

// ---------------------------------------------------------------------------
// Problem constants (fixed by setup_inputs)
// ---------------------------------------------------------------------------
namespace {
constexpr int kBN   = 16;
constexpr int kT    = 12;
constexpr int kCH   = 128;
constexpr int kH    = 24, kW = 24;
constexpr int kHW   = 576;
constexpr int kTm1  = 11;
constexpr int kTp   = 9;
constexpr int kNB   = 144;    // kBN * kTp
constexpr int kVCH  = 146;
constexpr int kSSTA = 32;
constexpr int kCP   = 114;
constexpr int kNAtt = 176;    // kBN * kTm1
constexpr float kScale = 0.0883883476483184f;  // 128^-0.5
constexpr int kKT   = 64;     // K-elements per SMEM tile (halves)
constexpr int kLds  = 72;     // smem row stride in halves (144 B, conflict-free)
}

// ---------------------------------------------------------------------------
// Low-level helpers
// ---------------------------------------------------------------------------
__device__ __forceinline__ unsigned long long pack2(float lo, float hi) {
    unsigned long long r;
    asm("mov.b64 %0, {%1, %2};" : "=l"(r) : "f"(lo), "f"(hi));
    return r;
}
__device__ __forceinline__ unsigned long long dup2(float v) { return pack2(v, v); }
__device__ __forceinline__ void ffma2(unsigned long long& d, unsigned long long a,
                                      unsigned long long b) {
    asm("fma.rn.f32x2 %0, %1, %2, %3;" : "=l"(d) : "l"(a), "l"(b), "l"(d));
}
__device__ __forceinline__ void unpack2(unsigned long long v, float& lo, float& hi) {
    asm("mov.b64 {%0, %1}, %2;" : "=f"(lo), "=f"(hi) : "l"(v));
}

// fp16 MMA m16n8k16 (legacy HMMA path -- valid on non-'a' sm_103 target)
__device__ __forceinline__ void mma16816(float* c, const uint32_t* a, const uint32_t* b) {
    asm volatile(
        "mma.sync.aligned.m16n8k16.row.col.f32.f16.f16.f32 "
        "{%0,%1,%2,%3}, {%4,%5,%6,%7}, {%8,%9}, {%0,%1,%2,%3};"
        : "+f"(c[0]), "+f"(c[1]), "+f"(c[2]), "+f"(c[3])
        : "r"(a[0]), "r"(a[1]), "r"(a[2]), "r"(a[3]), "r"(b[0]), "r"(b[1]));
}

__device__ __forceinline__ uint32_t smem_u32p(const void* p) {
    uint32_t a;
    asm("{ .reg .u64 t; cvta.to.shared.u64 t, %1; cvt.u32.u64 %0, t; }"
        : "=r"(a) : "l"(p));
    return a;
}
__device__ __forceinline__ void ldm_x4(uint32_t* r, uint32_t saddr) {
    asm volatile("ldmatrix.sync.aligned.m8n8.x4.shared.b16 {%0,%1,%2,%3}, [%4];"
                 : "=r"(r[0]), "=r"(r[1]), "=r"(r[2]), "=r"(r[3]) : "r"(saddr));
}
__device__ __forceinline__ void cpasync16(void* sdst, const void* gsrc) {
    asm volatile("cp.async.ca.shared.global [%0], [%1], 16;"
                 :: "r"(smem_u32p(sdst)), "l"(gsrc));
}
__device__ __forceinline__ void cp_commit() {
    asm volatile("cp.async.commit_group;" ::: "memory");
}
__device__ __forceinline__ void cp_wait1() {
    asm volatile("cp.async.wait_group 1;" ::: "memory");
}
__device__ __forceinline__ void cp_wait0() {
    asm volatile("cp.async.wait_group 0;" ::: "memory");
}

// pack two fp16 from floats
__device__ __forceinline__ uint32_t h2pack(float x, float y) {
    __half hx = __float2half_rn(x), hy = __float2half_rn(y);
    return ((uint32_t)__half_as_ushort(hy) << 16) | __half_as_ushort(hx);
}

// ---------------------------------------------------------------------------
// Scratch (static device globals)
// ---------------------------------------------------------------------------
__device__ __half g_xT[((size_t)kBN * kT * kHW + 64) * kCH];
// fp16 logits written by energy; softmax converts IN PLACE to attn probs.
__device__ __half g_attn_h[((size_t)kNAtt * kHW + 64) * kHW];
__device__ float g_vspe[kBN * kT * kVCH * kHW];
__device__ __half g_acc0[((size_t)kNB * kCP + 128) * kHW];
__device__ __half g_acc1[((size_t)kNB * 2 * kCP + 128) * kHW];
__device__ __half g_acc2[((size_t)kNB * 3 * kCP + 128) * kHW];

__device__ __forceinline__ __half* acc_buf(int s) {
    return s == 0 ? g_acc0 : (s == 1 ? g_acc1 : g_acc2);
}

// ---------------------------------------------------------------------------
// SMEM tile buffer (double-buffered). 128(m) x 128(n) CTA tile, K-tile = 64.
// 2 bufs * 36864 B = 73728 B/CTA -> 2 CTAs/SM (matches the ~94-reg cap and
// stays under the >=4-CTA L1tex contention regime measured in R9/R10).
// ---------------------------------------------------------------------------
struct Buf {
    __half Ah[128 * kLds];   // 18432 B
    __half Bh[128 * kLds];   // 18432 B
};
constexpr int kSmemDyn = 2 * sizeof(Buf);  // 73728 B

__device__ __forceinline__ void stage_tile(
    Buf& d, const __half* __restrict__ Agh, int lda,
    const __half* __restrict__ Bgh, int ldb, int k0, int tid) {
#pragma unroll
    for (int s = 0; s < 8; s++) {
        int i = s * 256 + tid;  // 0..2047; 8 float4-chunks per 64-half row
        int row = (i >> 3) & 127, c = i & 7;
        int coff = c * 8;
        if (i < 1024)
            cpasync16(&d.Ah[row * kLds + coff], Agh + (size_t)row * lda + k0 + coff);
        else
            cpasync16(&d.Bh[row * kLds + coff], Bgh + (size_t)row * ldb + k0 + coff);
    }
}

// Core: C[128x128] accumulate over K (multiple of 64). 8 warps = 4(m) x 2(n),
// warp tile 32(m) x 64(n). Fragments via ldmatrix.x4; pure fp16.
__device__ __forceinline__ void gemm_core(
    const __half* __restrict__ Agh, int lda,
    const __half* __restrict__ Bgh, int ldb,
    int K, float acc[2][8][4], Buf* bufs) {
    int tid = threadIdx.x;
    int wid = tid >> 5, lane = tid & 31;
    int wm = wid & 3, wn = wid >> 2;

    int j = lane >> 3, r = lane & 7;
    uint32_t aoff = (uint32_t)(((wm * 32 + ((j & 1) << 3) + r) * kLds + ((j >> 1) << 3)) * 2);
    uint32_t boff = (uint32_t)(((wn * 64 + ((j >> 1) << 3) + r) * kLds + ((j & 1) << 3)) * 2);

#pragma unroll
    for (int i = 0; i < 2; i++)
#pragma unroll
        for (int jj = 0; jj < 8; jj++)
#pragma unroll
            for (int q = 0; q < 4; q++) acc[i][jj][q] = 0.f;

    int nt = K / kKT;
    stage_tile(bufs[0], Agh, lda, Bgh, ldb, 0, tid);
    cp_commit();
    for (int kt = 0; kt < nt; kt++) {
        if (kt + 1 < nt) {
            stage_tile(bufs[(kt + 1) & 1], Agh, lda, Bgh, ldb, (kt + 1) * kKT, tid);
            cp_commit();
            cp_wait1();
        } else {
            cp_wait0();
        }
        __syncthreads();
        Buf& b = bufs[kt & 1];
        uint32_t Ah0 = smem_u32p(b.Ah) + aoff;
        uint32_t Bh0 = smem_u32p(b.Bh) + boff;
#pragma unroll
        for (int kb = 0; kb < 4; kb++) {
            uint32_t kbb = kb * 32;  // 16 halves = 32 bytes per k-step
            uint32_t ah[2][4];
            ldm_x4(ah[0], Ah0 + kbb);
            ldm_x4(ah[1], Ah0 + 16 * kLds * 2 + kbb);
#pragma unroll
            for (int half = 0; half < 2; half++) {
                uint32_t roff = (uint32_t)(half * 32 * kLds * 2) + kbb;
                uint32_t bhf[4][2];
                {
                    uint32_t t[4];
                    ldm_x4(t, Bh0 + roff);
                    bhf[0][0] = t[0]; bhf[0][1] = t[1]; bhf[1][0] = t[2]; bhf[1][1] = t[3];
                    ldm_x4(t, Bh0 + roff + 16 * kLds * 2);
                    bhf[2][0] = t[0]; bhf[2][1] = t[1]; bhf[3][0] = t[2]; bhf[3][1] = t[3];
                }
#pragma unroll
                for (int mi = 0; mi < 2; mi++)
#pragma unroll
                    for (int ni = 0; ni < 4; ni++)
                        mma16816(acc[mi][half * 4 + ni], ah[mi], bhf[ni]);
            }
        }
        __syncthreads();
    }
}

// ---------------------------------------------------------------------------
// 1) Normalize + transpose + fp16 convert: g_xT[bt*HW+pix][c]
// ---------------------------------------------------------------------------
__global__ __launch_bounds__(256) void normalize_t_kernel(const float* __restrict__ x) {
    __shared__ float sm[128][65];
    __shared__ float psum[4][64];
    __shared__ float invs[64];
    int bt = blockIdx.x, p0 = blockIdx.y * 64;
    int tid = threadIdx.x;
    int px = tid & 63, cq = tid >> 6;
    const float* xb = x + (size_t)bt * kCH * kHW + p0;
    float s = 0.f;
#pragma unroll
    for (int j = 0; j < 32; j++) {
        int c = cq * 32 + j;
        float v = xb[(size_t)c * kHW + px];
        sm[c][px] = v;
        s += v * v;
    }
    psum[cq][px] = s;
    __syncthreads();
    if (tid < 64) {
        float tot = psum[0][tid] + psum[1][tid] + psum[2][tid] + psum[3][tid];
        invs[tid] = 1.0f / fmaxf(sqrtf(tot), 1e-12f);
    }
    __syncthreads();
    float iv = invs[px];
    size_t rb = ((size_t)bt * kHW + p0 + px) * kCH + cq * 32;
#pragma unroll
    for (int j4 = 0; j4 < 8; j4++) {
        int c = cq * 32 + j4 * 4;
        uint32_t w0 = h2pack(sm[c][px] * iv, sm[c + 1][px] * iv);
        uint32_t w1 = h2pack(sm[c + 2][px] * iv, sm[c + 3][px] * iv);
        *(uint2*)(g_xT + rb + j4 * 4) = make_uint2(w0, w1);
    }
}

// ---------------------------------------------------------------------------
// 2) Value projection (FFMA2 SIMT): vs_pe = Wv @ x + bv
// ---------------------------------------------------------------------------
__global__ __launch_bounds__(256) void vproj_kernel(const float* __restrict__ x,
                                                    const float* __restrict__ Wv,
                                                    const float* __restrict__ bv) {
    int bt = blockIdx.y;
    int p0 = blockIdx.x * 64;
    __shared__ __align__(16) float Ws[16][132];
    __shared__ __align__(16) float Xs[16][68];
    int tid = threadIdx.x;
    int ty = tid >> 4, tx = tid & 15;
    unsigned long long acc[4][4];
#pragma unroll
    for (int i = 0; i < 4; i++)
#pragma unroll
        for (int j = 0; j < 4; j++) acc[i][j] = 0ULL;

    const float* xb = x + (size_t)bt * kCH * kHW;
    for (int c0 = 0; c0 < kCH; c0 += 16) {
#pragma unroll
        for (int r = 0; r < 8; r++) {
            int lin = r * 256 + tid;
            int o = lin >> 4, c = lin & 15;
            Ws[c][o] = Wv[o * kCH + c0 + c];
        }
#pragma unroll
        for (int r = 0; r < 4; r++) {
            int lin = r * 256 + tid;
            int c = lin >> 6, j = lin & 63;
            Xs[c][j] = xb[(size_t)(c0 + c) * kHW + p0 + j];
        }
        __syncthreads();
#pragma unroll
        for (int c = 0; c < 16; c++) {
            float4 xv = *(const float4*)&Xs[c][tx * 4];
            float4 w0 = *(const float4*)&Ws[c][ty * 8];
            float4 w1 = *(const float4*)&Ws[c][ty * 8 + 4];
            unsigned long long wp[4] = {pack2(w0.x, w0.y), pack2(w0.z, w0.w),
                                        pack2(w1.x, w1.y), pack2(w1.z, w1.w)};
            unsigned long long xd[4] = {dup2(xv.x), dup2(xv.y), dup2(xv.z), dup2(xv.w)};
#pragma unroll
            for (int i = 0; i < 4; i++)
#pragma unroll
                for (int j = 0; j < 4; j++) ffma2(acc[i][j], wp[i], xd[j]);
        }
        __syncthreads();
    }
    float* ob = g_vspe + (size_t)bt * kVCH * kHW;
#pragma unroll
    for (int i = 0; i < 4; i++) {
        int o = ty * 8 + 2 * i;
        float b0 = bv[o], b1 = bv[o + 1];
#pragma unroll
        for (int j = 0; j < 4; j++) {
            float lo, hi;
            unpack2(acc[i][j], lo, hi);
            ob[(size_t)o * kHW + p0 + tx * 4 + j] = lo + b0;
            ob[(size_t)(o + 1) * kHW + p0 + tx * 4 + j] = hi + b1;
        }
    }
}

// ---------------------------------------------------------------------------
// 3) Positional-encoding channels 128..145 of vs_pe
// ---------------------------------------------------------------------------
__global__ __launch_bounds__(256) void pe_fill_kernel() {
    int gid = blockIdx.x * 256 + threadIdx.x;
    const int total = kBN * kT * 18 * kHW;
    if (gid >= total) return;
    int bt  = gid / (18 * kHW);
    int rem = gid % (18 * kHW);
    int c = rem / kHW, pix = rem % kHW;
    int yy = pix / kW, xx = pix % kW;
    float yc = -1.0f + 2.0f * (float)yy / (float)(kH - 1);
    float xc = -1.0f + 2.0f * (float)xx / (float)(kW - 1);
    float val;
    if (c == 0) val = yc;
    else if (c == 1) val = xc;
    else {
        int i = (c - 2) >> 2;
        int k = (c - 2) & 3;
        float coord = (k & 1) ? xc : yc;
        float f = (float)(1 << i) * 3.14159265358979323846f * coord;
        val = (k < 2) ? sinf(f) : cosf(f);
    }
    g_vspe[(size_t)bt * kVCH * kHW + (size_t)(kCH + c) * kHW + pix] = val;
}

// ---------------------------------------------------------------------------
// 4) Energy GEMM: logits[g,n,m] = scale * sum_c qT[n,c]*kT[m,c]; out fp16.
//    grid = (5 m-tiles(128), 5 n-tiles(128), 176 g)
// ---------------------------------------------------------------------------
__global__ __launch_bounds__(256) void energy_mma_kernel() {
    extern __shared__ __align__(16) char smem[];
    int g = blockIdx.z;
    int b = g / kTm1, t = g % kTm1;
    int m0 = blockIdx.y * 128, n0 = blockIdx.x * 128;
    size_t abase = ((size_t)(b * kT + t + 1) * kHW + m0) * kCH;
    size_t bbase = ((size_t)(b * kT + t) * kHW + n0) * kCH;
    float acc[2][8][4];
    gemm_core(g_xT + abase, kCH, g_xT + bbase, kCH, kCH, acc, (Buf*)smem);

    int tid = threadIdx.x;
    int wid = tid >> 5, lane = tid & 31;
    int quad = lane >> 2, tq = lane & 3;
    int wm = wid & 3, wn = wid >> 2;
    int mvalid = kHW - m0;
    __half* C = g_attn_h + (size_t)g * kHW * kHW + (size_t)m0 * kHW;
#pragma unroll
    for (int mi = 0; mi < 2; mi++)
#pragma unroll
        for (int rh = 0; rh < 2; rh++) {
            int rrow = wm * 32 + mi * 16 + quad + rh * 8;
            if (rrow < mvalid) {
#pragma unroll
                for (int ni = 0; ni < 8; ni++) {
                    int ncol = n0 + wn * 64 + ni * 8 + tq * 2;
                    if (ncol < kHW) {
                        uint32_t hw = h2pack(acc[mi][ni][rh * 2] * kScale,
                                             acc[mi][ni][rh * 2 + 1] * kScale);
                        *(uint32_t*)(C + (size_t)rrow * kHW + ncol) = hw;
                    }
                }
            }
        }
}

// ---------------------------------------------------------------------------
// 5) Softmax row-wise, IN PLACE on fp16 logits -> fp16 probabilities
// ---------------------------------------------------------------------------
__global__ __launch_bounds__(256) void softmax_kernel() {
    size_t row = blockIdx.x;
    __half* p = g_attn_h + row * (size_t)kHW;
    int tid = threadIdx.x;
    int lane = tid & 31, wid = tid >> 5;
    __shared__ float redm[8], reds[8];

    float a = __half2float(p[tid]);
    float b = __half2float(p[tid + 256]);
    float c = (tid < 64) ? __half2float(p[tid + 512]) : -3.0e38f;
    float m = fmaxf(fmaxf(a, b), c);
#pragma unroll
    for (int off = 16; off > 0; off >>= 1) m = fmaxf(m, __shfl_xor_sync(0xffffffffu, m, off));
    if (lane == 0) redm[wid] = m;
    __syncthreads();
    float bm = redm[0];
#pragma unroll
    for (int w = 1; w < 8; w++) bm = fmaxf(bm, redm[w]);

    float e0 = expf(a - bm);
    float e1 = expf(b - bm);
    float e2 = (tid < 64) ? expf(c - bm) : 0.f;
    float s = e0 + e1 + e2;
#pragma unroll
    for (int off = 16; off > 0; off >>= 1) s += __shfl_xor_sync(0xffffffffu, s, off);
    if (lane == 0) reds[wid] = s;
    __syncthreads();
    float tot = reds[0];
#pragma unroll
    for (int w = 1; w < 8; w++) tot += reds[w];
    float inv = 1.0f / tot;

    __syncthreads();  // all reads done before in-place writes
    p[tid] = __float2half_rn(e0 * inv);
    p[tid + 256] = __float2half_rn(e1 * inv);
    if (tid < 64) p[tid + 512] = __float2half_rn(e2 * inv);
}

// ---------------------------------------------------------------------------
// 6) Copy "cs" slice from vs_pe. dstSel<3: fp16; dstSel==3: fp32 out.
// ---------------------------------------------------------------------------
__global__ __launch_bounds__(256) void copy_cs_kernel(int dstSel, float* outp,
                                                      int dstC, int t0) {
    int gid = blockIdx.x * 256 + threadIdx.x;
    const int total = kNB * kCP * kHW;
    if (gid >= total) return;
    int bz = gid / (kCP * kHW);
    int rem = gid % (kCP * kHW);
    int c = rem / kHW, pix = rem % kHW;
    int b = bz / kTp, t = bz % kTp;
    float v = g_vspe[((size_t)b * kT + t + t0) * kVCH * kHW + (size_t)(kSSTA + c) * kHW + pix];
    size_t di = (size_t)bz * dstC * kHW + (size_t)c * kHW + pix;
    if (dstSel == 3) {
        outp[di] = v;
    } else {
        acc_buf(dstSel)[di] = __float2half_rn(v);
    }
}

// ---------------------------------------------------------------------------
// 7) Propagation GEMM: dst[bz,114+c,n] = sum_m A[bz,c,m]*attn[b,t0+t,n,m]
//    grid = (5 n-tiles(128), Mtiles(128), 144 bz).
// ---------------------------------------------------------------------------
__global__ __launch_bounds__(256) void prop_mma_kernel(int dstSel, float* outp, int srcSel,
                                                       int dstC, int Cin, int t0) {
    extern __shared__ __align__(16) char smem[];
    int bz = blockIdx.z;
    int b = bz / kTp, t = bz % kTp;
    int c0 = blockIdx.y * 128, n0 = blockIdx.x * 128;
    size_t abase = ((size_t)bz * Cin + c0) * kHW;
    size_t bbase = ((size_t)b * kTm1 + t0 + t) * kHW * kHW + (size_t)n0 * kHW;
    float acc[2][8][4];
    gemm_core(acc_buf(srcSel) + abase, kHW, g_attn_h + bbase, kHW, kHW, acc, (Buf*)smem);

    int tid = threadIdx.x;
    int wid = tid >> 5, lane = tid & 31;
    int quad = lane >> 2, tq = lane & 3;
    int wm = wid & 3, wn = wid >> 2;
#pragma unroll
    for (int mi = 0; mi < 2; mi++)
#pragma unroll
        for (int rh = 0; rh < 2; rh++) {
            int rloc = wm * 32 + mi * 16 + quad + rh * 8;
            int cg = c0 + rloc;
            if (cg < Cin) {
                size_t rbase = ((size_t)bz * dstC + kCP + cg) * kHW;
#pragma unroll
                for (int ni = 0; ni < 8; ni++) {
                    int ncol = n0 + wn * 64 + ni * 8 + tq * 2;
                    if (ncol < kHW) {
                        if (dstSel == 3) {
                            float2 v = make_float2(acc[mi][ni][rh * 2],
                                                   acc[mi][ni][rh * 2 + 1]);
                            *(float2*)(outp + rbase + ncol) = v;
                        } else {
                            uint32_t hw = h2pack(acc[mi][ni][rh * 2],
                                                 acc[mi][ni][rh * 2 + 1]);
                            *(uint32_t*)(acc_buf(dstSel) + rbase + ncol) = hw;
                        }
                    }
                }
            }
        }
}

// ---------------------------------------------------------------------------
extern "C" void kernel_launch(void* const* d_in, const int* in_sizes, int n_in,
                              void* d_out, int out_size) {
    const float* x  = (const float*)d_in[0];
    const float* Wv = (const float*)d_in[1];
    const float* bv = (const float*)d_in[2];
    float* out = (float*)d_out;

    static bool attrs_set = false;
    if (!attrs_set) {
        cudaFuncSetAttribute(energy_mma_kernel,
                             cudaFuncAttributeMaxDynamicSharedMemorySize, kSmemDyn);
        cudaFuncSetAttribute(prop_mma_kernel,
                             cudaFuncAttributeMaxDynamicSharedMemorySize, kSmemDyn);
        attrs_set = true;
    }

    normalize_t_kernel<<<dim3(kBN * kT, kHW / 64), 256>>>(x);
    vproj_kernel<<<dim3(kHW / 64, kBN * kT), 256>>>(x, Wv, bv);
    pe_fill_kernel<<<(kBN * kT * 18 * kHW + 255) / 256, 256>>>();
    energy_mma_kernel<<<dim3(5, 5, kNAtt), 256, kSmemDyn>>>();
    softmax_kernel<<<kNAtt * kHW, 256>>>();
    const int copyG = (kNB * kCP * kHW + 255) / 256;
    copy_cs_kernel<<<copyG, 256>>>(0, out, kCP, 0);
    prop_mma_kernel<<<dim3(5, 1, kNB), 256, kSmemDyn>>>(1, out, 0, 2 * kCP, kCP, 0);
    copy_cs_kernel<<<copyG, 256>>>(1, out, 2 * kCP, 1);
    prop_mma_kernel<<<dim3(5, 2, kNB), 256, kSmemDyn>>>(2, out, 1, 3 * kCP, 2 * kCP, 1);
    copy_cs_kernel<<<copyG, 256>>>(2, out, 3 * kCP, 2);
    prop_mma_kernel<<<dim3(5, 3, kNB), 256, kSmemDyn>>>(3, out, 2, 4 * kCP, 3 * kCP, 2);
    copy_cs_kernel<<<copyG, 256>>>(3, out, 4 * kCP, 3);
}

// round 14
// speedup vs baseline: 3.2486x; 1.2445x over previous
#include <cuda_runtime.h>
#include <cuda_fp16.h>
#include <math.h>
#include <cstdint>

// ---------------------------------------------------------------------------
// Problem constants (fixed by setup_inputs)
// ---------------------------------------------------------------------------
namespace {
constexpr int kBN   = 16;
constexpr int kT    = 12;
constexpr int kCH   = 128;
constexpr int kH    = 24, kW = 24;
constexpr int kHW   = 576;
constexpr int kTm1  = 11;
constexpr int kTp   = 9;
constexpr int kNB   = 144;    // kBN * kTp
constexpr int kSSTA = 32;
constexpr int kCP   = 114;
constexpr int kOutC = 456;    // 4 * kCP
constexpr int kNAtt = 176;    // kBN * kTm1
constexpr float kScale = 0.0883883476483184f;  // 128^-0.5
constexpr int kKT   = 64;     // K-elements per SMEM tile (halves)
constexpr int kLds  = 72;     // smem row stride in halves (144 B, conflict-free)
}

// ---------------------------------------------------------------------------
// Low-level helpers
// ---------------------------------------------------------------------------
__device__ __forceinline__ unsigned long long pack2(float lo, float hi) {
    unsigned long long r;
    asm("mov.b64 %0, {%1, %2};" : "=l"(r) : "f"(lo), "f"(hi));
    return r;
}
__device__ __forceinline__ unsigned long long dup2(float v) { return pack2(v, v); }
__device__ __forceinline__ void ffma2(unsigned long long& d, unsigned long long a,
                                      unsigned long long b) {
    asm("fma.rn.f32x2 %0, %1, %2, %3;" : "=l"(d) : "l"(a), "l"(b), "l"(d));
}
__device__ __forceinline__ void unpack2(unsigned long long v, float& lo, float& hi) {
    asm("mov.b64 {%0, %1}, %2;" : "=f"(lo), "=f"(hi) : "l"(v));
}

// fp16 MMA m16n8k16 (legacy HMMA path -- valid on non-'a' sm_103 target)
__device__ __forceinline__ void mma16816(float* c, const uint32_t* a, const uint32_t* b) {
    asm volatile(
        "mma.sync.aligned.m16n8k16.row.col.f32.f16.f16.f32 "
        "{%0,%1,%2,%3}, {%4,%5,%6,%7}, {%8,%9}, {%0,%1,%2,%3};"
        : "+f"(c[0]), "+f"(c[1]), "+f"(c[2]), "+f"(c[3])
        : "r"(a[0]), "r"(a[1]), "r"(a[2]), "r"(a[3]), "r"(b[0]), "r"(b[1]));
}

__device__ __forceinline__ uint32_t smem_u32p(const void* p) {
    uint32_t a;
    asm("{ .reg .u64 t; cvta.to.shared.u64 t, %1; cvt.u32.u64 %0, t; }"
        : "=r"(a) : "l"(p));
    return a;
}
__device__ __forceinline__ void ldm_x4(uint32_t* r, uint32_t saddr) {
    asm volatile("ldmatrix.sync.aligned.m8n8.x4.shared.b16 {%0,%1,%2,%3}, [%4];"
                 : "=r"(r[0]), "=r"(r[1]), "=r"(r[2]), "=r"(r[3]) : "r"(saddr));
}
__device__ __forceinline__ void cpasync16(void* sdst, const void* gsrc) {
    asm volatile("cp.async.ca.shared.global [%0], [%1], 16;"
                 :: "r"(smem_u32p(sdst)), "l"(gsrc));
}
__device__ __forceinline__ void cp_commit() {
    asm volatile("cp.async.commit_group;" ::: "memory");
}
__device__ __forceinline__ void cp_wait1() {
    asm volatile("cp.async.wait_group 1;" ::: "memory");
}
__device__ __forceinline__ void cp_wait0() {
    asm volatile("cp.async.wait_group 0;" ::: "memory");
}

// pack two fp16 from floats
__device__ __forceinline__ uint32_t h2pack(float x, float y) {
    __half hx = __float2half_rn(x), hy = __float2half_rn(y);
    return ((uint32_t)__half_as_ushort(hy) << 16) | __half_as_ushort(hx);
}

// ---------------------------------------------------------------------------
// Scratch (static device globals)
// ---------------------------------------------------------------------------
__device__ __half g_xT[((size_t)kBN * kT * kHW + 64) * kCH];
// fp16 logits written by energy; softmax converts IN PLACE to attn probs.
__device__ __half g_attn_h[((size_t)kNAtt * kHW + 64) * kHW];
__device__ __half g_acc0[((size_t)kNB * kCP + 128) * kHW];
__device__ __half g_acc1[((size_t)kNB * 2 * kCP + 128) * kHW];
__device__ __half g_acc2[((size_t)kNB * 3 * kCP + 128) * kHW];

__device__ __forceinline__ __half* acc_buf(int s) {
    return s == 0 ? g_acc0 : (s == 1 ? g_acc1 : g_acc2);
}

// ---------------------------------------------------------------------------
// SMEM tile buffer (double-buffered). 128(m) x 128(n) CTA tile, K-tile = 64.
// 2 bufs * 36864 B = 73728 B/CTA -> 2 CTAs/SM (matches the ~98-reg cap and
// stays under the >=4-CTA L1tex contention regime measured in R9/R10).
// ---------------------------------------------------------------------------
struct Buf {
    __half Ah[128 * kLds];   // 18432 B
    __half Bh[128 * kLds];   // 18432 B
};
constexpr int kSmemDyn = 2 * sizeof(Buf);  // 73728 B

__device__ __forceinline__ void stage_tile(
    Buf& d, const __half* __restrict__ Agh, int lda,
    const __half* __restrict__ Bgh, int ldb, int k0, int tid) {
#pragma unroll
    for (int s = 0; s < 8; s++) {
        int i = s * 256 + tid;  // 0..2047; 8 float4-chunks per 64-half row
        int row = (i >> 3) & 127, c = i & 7;
        int coff = c * 8;
        if (i < 1024)
            cpasync16(&d.Ah[row * kLds + coff], Agh + (size_t)row * lda + k0 + coff);
        else
            cpasync16(&d.Bh[row * kLds + coff], Bgh + (size_t)row * ldb + k0 + coff);
    }
}

// Core: C[128x128] accumulate over K (multiple of 64). 8 warps = 4(m) x 2(n),
// warp tile 32(m) x 64(n). Fragments via ldmatrix.x4; pure fp16.
__device__ __forceinline__ void gemm_core(
    const __half* __restrict__ Agh, int lda,
    const __half* __restrict__ Bgh, int ldb,
    int K, float acc[2][8][4], Buf* bufs) {
    int tid = threadIdx.x;
    int wid = tid >> 5, lane = tid & 31;
    int wm = wid & 3, wn = wid >> 2;

    int j = lane >> 3, r = lane & 7;
    uint32_t aoff = (uint32_t)(((wm * 32 + ((j & 1) << 3) + r) * kLds + ((j >> 1) << 3)) * 2);
    uint32_t boff = (uint32_t)(((wn * 64 + ((j >> 1) << 3) + r) * kLds + ((j & 1) << 3)) * 2);

#pragma unroll
    for (int i = 0; i < 2; i++)
#pragma unroll
        for (int jj = 0; jj < 8; jj++)
#pragma unroll
            for (int q = 0; q < 4; q++) acc[i][jj][q] = 0.f;

    int nt = K / kKT;
    stage_tile(bufs[0], Agh, lda, Bgh, ldb, 0, tid);
    cp_commit();
    for (int kt = 0; kt < nt; kt++) {
        if (kt + 1 < nt) {
            stage_tile(bufs[(kt + 1) & 1], Agh, lda, Bgh, ldb, (kt + 1) * kKT, tid);
            cp_commit();
            cp_wait1();
        } else {
            cp_wait0();
        }
        __syncthreads();
        Buf& b = bufs[kt & 1];
        uint32_t Ah0 = smem_u32p(b.Ah) + aoff;
        uint32_t Bh0 = smem_u32p(b.Bh) + boff;
#pragma unroll
        for (int kb = 0; kb < 4; kb++) {
            uint32_t kbb = kb * 32;  // 16 halves = 32 bytes per k-step
            uint32_t ah[2][4];
            ldm_x4(ah[0], Ah0 + kbb);
            ldm_x4(ah[1], Ah0 + 16 * kLds * 2 + kbb);
#pragma unroll
            for (int half = 0; half < 2; half++) {
                uint32_t roff = (uint32_t)(half * 32 * kLds * 2) + kbb;
                uint32_t bhf[4][2];
                {
                    uint32_t t[4];
                    ldm_x4(t, Bh0 + roff);
                    bhf[0][0] = t[0]; bhf[0][1] = t[1]; bhf[1][0] = t[2]; bhf[1][1] = t[3];
                    ldm_x4(t, Bh0 + roff + 16 * kLds * 2);
                    bhf[2][0] = t[0]; bhf[2][1] = t[1]; bhf[3][0] = t[2]; bhf[3][1] = t[3];
                }
#pragma unroll
                for (int mi = 0; mi < 2; mi++)
#pragma unroll
                    for (int ni = 0; ni < 4; ni++)
                        mma16816(acc[mi][half * 4 + ni], ah[mi], bhf[ni]);
            }
        }
        __syncthreads();
    }
}

// ---------------------------------------------------------------------------
// 1) Normalize + transpose + fp16 convert: g_xT[bt*HW+pix][c]
// ---------------------------------------------------------------------------
__global__ __launch_bounds__(256) void normalize_t_kernel(const float* __restrict__ x) {
    __shared__ float sm[128][65];
    __shared__ float psum[4][64];
    __shared__ float invs[64];
    int bt = blockIdx.x, p0 = blockIdx.y * 64;
    int tid = threadIdx.x;
    int px = tid & 63, cq = tid >> 6;
    const float* xb = x + (size_t)bt * kCH * kHW + p0;
    float s = 0.f;
#pragma unroll
    for (int j = 0; j < 32; j++) {
        int c = cq * 32 + j;
        float v = xb[(size_t)c * kHW + px];
        sm[c][px] = v;
        s += v * v;
    }
    psum[cq][px] = s;
    __syncthreads();
    if (tid < 64) {
        float tot = psum[0][tid] + psum[1][tid] + psum[2][tid] + psum[3][tid];
        invs[tid] = 1.0f / fmaxf(sqrtf(tot), 1e-12f);
    }
    __syncthreads();
    float iv = invs[px];
    size_t rb = ((size_t)bt * kHW + p0 + px) * kCH + cq * 32;
#pragma unroll
    for (int j4 = 0; j4 < 8; j4++) {
        int c = cq * 32 + j4 * 4;
        uint32_t w0 = h2pack(sm[c][px] * iv, sm[c + 1][px] * iv);
        uint32_t w1 = h2pack(sm[c + 2][px] * iv, sm[c + 3][px] * iv);
        *(uint2*)(g_xT + rb + j4 * 4) = make_uint2(w0, w1);
    }
}

// ---------------------------------------------------------------------------
// 2) Value projection FUSED with cs-scatter. Computes only channels 32..127
//    (channels 0..31 are dropped by the S_STA slice) and writes each value
//    directly into acc0/acc1/acc2 (fp16) and out (fp32) for every stage s
//    where t = tt - s lies in [0, kTp).  cs channel = o - 32.
//    Tile: 96(ch) x 64(pix) per bt; 256 thr; 6x4 microtile (FFMA2 pairs).
// ---------------------------------------------------------------------------
__global__ __launch_bounds__(256) void vproj_fused_kernel(const float* __restrict__ x,
                                                          const float* __restrict__ Wv,
                                                          const float* __restrict__ bv,
                                                          float* __restrict__ outp) {
    int bt = blockIdx.y;
    int p0 = blockIdx.x * 64;
    int b = bt / kT, tt = bt % kT;
    __shared__ __align__(16) float Ws[16][100];  // [c][o'] o'=0..95
    __shared__ __align__(16) float Xs[16][68];
    int tid = threadIdx.x;
    int ty = tid >> 4, tx = tid & 15;
    unsigned long long acc[3][4];
#pragma unroll
    for (int i = 0; i < 3; i++)
#pragma unroll
        for (int j = 0; j < 4; j++) acc[i][j] = 0ULL;

    const float* xb = x + (size_t)bt * kCH * kHW;
    for (int c0 = 0; c0 < kCH; c0 += 16) {
#pragma unroll
        for (int r = 0; r < 6; r++) {            // 96 o x 16 c
            int lin = r * 256 + tid;
            int o = lin >> 4, c = lin & 15;
            Ws[c][o] = Wv[(kSSTA + o) * kCH + c0 + c];
        }
#pragma unroll
        for (int r = 0; r < 4; r++) {
            int lin = r * 256 + tid;
            int c = lin >> 6, j = lin & 63;
            Xs[c][j] = xb[(size_t)(c0 + c) * kHW + p0 + j];
        }
        __syncthreads();
#pragma unroll
        for (int c = 0; c < 16; c++) {
            float4 xv = *(const float4*)&Xs[c][tx * 4];
            float w0 = Ws[c][ty * 6 + 0], w1 = Ws[c][ty * 6 + 1];
            float w2 = Ws[c][ty * 6 + 2], w3 = Ws[c][ty * 6 + 3];
            float w4 = Ws[c][ty * 6 + 4], w5 = Ws[c][ty * 6 + 5];
            unsigned long long wp[3] = {pack2(w0, w1), pack2(w2, w3), pack2(w4, w5)};
            unsigned long long xd[4] = {dup2(xv.x), dup2(xv.y), dup2(xv.z), dup2(xv.w)};
#pragma unroll
            for (int i = 0; i < 3; i++)
#pragma unroll
                for (int j = 0; j < 4; j++) ffma2(acc[i][j], wp[i], xd[j]);
        }
        __syncthreads();
    }

    // Epilogue: scatter each channel row (4 pix values) to all valid stages.
#pragma unroll
    for (int i = 0; i < 3; i++) {
        int cd0 = ty * 6 + 2 * i;               // cs channel of 'lo' lane
        float b0 = bv[kSSTA + cd0], b1 = bv[kSSTA + cd0 + 1];
        float vlo[4], vhi[4];
#pragma unroll
        for (int j = 0; j < 4; j++) {
            float lo, hi;
            unpack2(acc[i][j], lo, hi);
            vlo[j] = lo + b0;
            vhi[j] = hi + b1;
        }
        int pix = p0 + tx * 4;
        uint2 hlo = make_uint2(h2pack(vlo[0], vlo[1]), h2pack(vlo[2], vlo[3]));
        uint2 hhi = make_uint2(h2pack(vhi[0], vhi[1]), h2pack(vhi[2], vhi[3]));
#pragma unroll
        for (int s = 0; s < 4; s++) {
            int t = tt - s;
            if (t >= 0 && t < kTp) {
                int bz = b * kTp + t;
                if (s == 3) {
                    float* d = outp + ((size_t)bz * kOutC + cd0) * kHW + pix;
                    *(float4*)d = make_float4(vlo[0], vlo[1], vlo[2], vlo[3]);
                    *(float4*)(d + kHW) = make_float4(vhi[0], vhi[1], vhi[2], vhi[3]);
                } else {
                    int dc = (s + 1) * kCP;
                    __half* d = acc_buf(s) + ((size_t)bz * dc + cd0) * kHW + pix;
                    *(uint2*)d = hlo;
                    *(uint2*)(d + kHW) = hhi;
                }
            }
        }
    }
}

// ---------------------------------------------------------------------------
// 3) Positional-encoding FUSED scatter: cs channels 96..113 for all stages.
// ---------------------------------------------------------------------------
__global__ __launch_bounds__(256) void pe_fill_fused_kernel(float* __restrict__ outp) {
    int gid = blockIdx.x * 256 + threadIdx.x;
    const int total = kBN * kT * 18 * kHW;
    if (gid >= total) return;
    int bt  = gid / (18 * kHW);
    int rem = gid % (18 * kHW);
    int c = rem / kHW, pix = rem % kHW;
    int yy = pix / kW, xx = pix % kW;
    float yc = -1.0f + 2.0f * (float)yy / (float)(kH - 1);
    float xc = -1.0f + 2.0f * (float)xx / (float)(kW - 1);
    float val;
    if (c == 0) val = yc;
    else if (c == 1) val = xc;
    else {
        int i = (c - 2) >> 2;
        int k = (c - 2) & 3;
        float coord = (k & 1) ? xc : yc;
        float f = (float)(1 << i) * 3.14159265358979323846f * coord;
        val = (k < 2) ? sinf(f) : cosf(f);
    }
    int b = bt / kT, tt = bt % kT;
    int cd = 96 + c;
    __half hv = __float2half_rn(val);
#pragma unroll
    for (int s = 0; s < 4; s++) {
        int t = tt - s;
        if (t >= 0 && t < kTp) {
            int bz = b * kTp + t;
            if (s == 3)
                outp[((size_t)bz * kOutC + cd) * kHW + pix] = val;
            else
                acc_buf(s)[((size_t)bz * (s + 1) * kCP + cd) * kHW + pix] = hv;
        }
    }
}

// ---------------------------------------------------------------------------
// 4) Energy GEMM: logits[g,n,m] = scale * sum_c qT[n,c]*kT[m,c]; out fp16.
//    grid = (5 m-tiles(128), 5 n-tiles(128), 176 g)
// ---------------------------------------------------------------------------
__global__ __launch_bounds__(256) void energy_mma_kernel() {
    extern __shared__ __align__(16) char smem[];
    int g = blockIdx.z;
    int b = g / kTm1, t = g % kTm1;
    int m0 = blockIdx.y * 128, n0 = blockIdx.x * 128;
    size_t abase = ((size_t)(b * kT + t + 1) * kHW + m0) * kCH;
    size_t bbase = ((size_t)(b * kT + t) * kHW + n0) * kCH;
    float acc[2][8][4];
    gemm_core(g_xT + abase, kCH, g_xT + bbase, kCH, kCH, acc, (Buf*)smem);

    int tid = threadIdx.x;
    int wid = tid >> 5, lane = tid & 31;
    int quad = lane >> 2, tq = lane & 3;
    int wm = wid & 3, wn = wid >> 2;
    int mvalid = kHW - m0;
    __half* C = g_attn_h + (size_t)g * kHW * kHW + (size_t)m0 * kHW;
#pragma unroll
    for (int mi = 0; mi < 2; mi++)
#pragma unroll
        for (int rh = 0; rh < 2; rh++) {
            int rrow = wm * 32 + mi * 16 + quad + rh * 8;
            if (rrow < mvalid) {
#pragma unroll
                for (int ni = 0; ni < 8; ni++) {
                    int ncol = n0 + wn * 64 + ni * 8 + tq * 2;
                    if (ncol < kHW) {
                        uint32_t hw = h2pack(acc[mi][ni][rh * 2] * kScale,
                                             acc[mi][ni][rh * 2 + 1] * kScale);
                        *(uint32_t*)(C + (size_t)rrow * kHW + ncol) = hw;
                    }
                }
            }
        }
}

// ---------------------------------------------------------------------------
// 5) Softmax row-wise, IN PLACE on fp16 logits -> fp16 probabilities
// ---------------------------------------------------------------------------
__global__ __launch_bounds__(256) void softmax_kernel() {
    size_t row = blockIdx.x;
    __half* p = g_attn_h + row * (size_t)kHW;
    int tid = threadIdx.x;
    int lane = tid & 31, wid = tid >> 5;
    __shared__ float redm[8], reds[8];

    float a = __half2float(p[tid]);
    float b = __half2float(p[tid + 256]);
    float c = (tid < 64) ? __half2float(p[tid + 512]) : -3.0e38f;
    float m = fmaxf(fmaxf(a, b), c);
#pragma unroll
    for (int off = 16; off > 0; off >>= 1) m = fmaxf(m, __shfl_xor_sync(0xffffffffu, m, off));
    if (lane == 0) redm[wid] = m;
    __syncthreads();
    float bm = redm[0];
#pragma unroll
    for (int w = 1; w < 8; w++) bm = fmaxf(bm, redm[w]);

    float e0 = expf(a - bm);
    float e1 = expf(b - bm);
    float e2 = (tid < 64) ? expf(c - bm) : 0.f;
    float s = e0 + e1 + e2;
#pragma unroll
    for (int off = 16; off > 0; off >>= 1) s += __shfl_xor_sync(0xffffffffu, s, off);
    if (lane == 0) reds[wid] = s;
    __syncthreads();
    float tot = reds[0];
#pragma unroll
    for (int w = 1; w < 8; w++) tot += reds[w];
    float inv = 1.0f / tot;

    __syncthreads();  // all reads done before in-place writes
    p[tid] = __float2half_rn(e0 * inv);
    p[tid + 256] = __float2half_rn(e1 * inv);
    if (tid < 64) p[tid + 512] = __float2half_rn(e2 * inv);
}

// ---------------------------------------------------------------------------
// 6) Propagation GEMM: dst[bz,114+c,n] = sum_m A[bz,c,m]*attn[b,t0+t,n,m]
//    grid = (5 n-tiles(128), Mtiles(128), 144 bz).
// ---------------------------------------------------------------------------
__global__ __launch_bounds__(256) void prop_mma_kernel(int dstSel, float* outp, int srcSel,
                                                       int dstC, int Cin, int t0) {
    extern __shared__ __align__(16) char smem[];
    int bz = blockIdx.z;
    int b = bz / kTp, t = bz % kTp;
    int c0 = blockIdx.y * 128, n0 = blockIdx.x * 128;
    size_t abase = ((size_t)bz * Cin + c0) * kHW;
    size_t bbase = ((size_t)b * kTm1 + t0 + t) * kHW * kHW + (size_t)n0 * kHW;
    float acc[2][8][4];
    gemm_core(acc_buf(srcSel) + abase, kHW, g_attn_h + bbase, kHW, kHW, acc, (Buf*)smem);

    int tid = threadIdx.x;
    int wid = tid >> 5, lane = tid & 31;
    int quad = lane >> 2, tq = lane & 3;
    int wm = wid & 3, wn = wid >> 2;
#pragma unroll
    for (int mi = 0; mi < 2; mi++)
#pragma unroll
        for (int rh = 0; rh < 2; rh++) {
            int rloc = wm * 32 + mi * 16 + quad + rh * 8;
            int cg = c0 + rloc;
            if (cg < Cin) {
                size_t rbase = ((size_t)bz * dstC + kCP + cg) * kHW;
#pragma unroll
                for (int ni = 0; ni < 8; ni++) {
                    int ncol = n0 + wn * 64 + ni * 8 + tq * 2;
                    if (ncol < kHW) {
                        if (dstSel == 3) {
                            float2 v = make_float2(acc[mi][ni][rh * 2],
                                                   acc[mi][ni][rh * 2 + 1]);
                            *(float2*)(outp + rbase + ncol) = v;
                        } else {
                            uint32_t hw = h2pack(acc[mi][ni][rh * 2],
                                                 acc[mi][ni][rh * 2 + 1]);
                            *(uint32_t*)(acc_buf(dstSel) + rbase + ncol) = hw;
                        }
                    }
                }
            }
        }
}

// ---------------------------------------------------------------------------
extern "C" void kernel_launch(void* const* d_in, const int* in_sizes, int n_in,
                              void* d_out, int out_size) {
    const float* x  = (const float*)d_in[0];
    const float* Wv = (const float*)d_in[1];
    const float* bv = (const float*)d_in[2];
    float* out = (float*)d_out;

    static bool attrs_set = false;
    if (!attrs_set) {
        cudaFuncSetAttribute(energy_mma_kernel,
                             cudaFuncAttributeMaxDynamicSharedMemorySize, kSmemDyn);
        cudaFuncSetAttribute(prop_mma_kernel,
                             cudaFuncAttributeMaxDynamicSharedMemorySize, kSmemDyn);
        attrs_set = true;
    }

    normalize_t_kernel<<<dim3(kBN * kT, kHW / 64), 256>>>(x);
    vproj_fused_kernel<<<dim3(kHW / 64, kBN * kT), 256>>>(x, Wv, bv, out);
    pe_fill_fused_kernel<<<(kBN * kT * 18 * kHW + 255) / 256, 256>>>(out);
    energy_mma_kernel<<<dim3(5, 5, kNAtt), 256, kSmemDyn>>>();
    softmax_kernel<<<kNAtt * kHW, 256>>>();
    prop_mma_kernel<<<dim3(5, 1, kNB), 256, kSmemDyn>>>(1, out, 0, 2 * kCP, kCP, 0);
    prop_mma_kernel<<<dim3(5, 2, kNB), 256, kSmemDyn>>>(2, out, 1, 3 * kCP, 2 * kCP, 1);
    prop_mma_kernel<<<dim3(5, 3, kNB), 256, kSmemDyn>>>(3, out, 2, 4 * kCP, 3 * kCP, 2);
}

// round 15
// speedup vs baseline: 3.7547x; 1.1558x over previous
#include <cuda_runtime.h>
#include <cuda_fp16.h>
#include <math.h>
#include <cstdint>

// ---------------------------------------------------------------------------
// Problem constants (fixed by setup_inputs)
// ---------------------------------------------------------------------------
namespace {
constexpr int kBN   = 16;
constexpr int kT    = 12;
constexpr int kCH   = 128;
constexpr int kH    = 24, kW = 24;
constexpr int kHW   = 576;
constexpr int kTm1  = 11;
constexpr int kTp   = 9;
constexpr int kNB   = 144;    // kBN * kTp
constexpr int kSSTA = 32;
constexpr int kCP   = 114;
constexpr int kOutC = 456;    // 4 * kCP
constexpr int kNAtt = 176;    // kBN * kTm1
constexpr float kScale = 0.0883883476483184f;  // 128^-0.5
constexpr int kKT   = 64;     // K-elements per SMEM tile (halves)
constexpr int kLds  = 72;     // smem row stride in halves (144 B, conflict-free)
}

// ---------------------------------------------------------------------------
// Low-level helpers
// ---------------------------------------------------------------------------
__device__ __forceinline__ unsigned long long pack2(float lo, float hi) {
    unsigned long long r;
    asm("mov.b64 %0, {%1, %2};" : "=l"(r) : "f"(lo), "f"(hi));
    return r;
}
__device__ __forceinline__ unsigned long long dup2(float v) { return pack2(v, v); }
__device__ __forceinline__ void ffma2(unsigned long long& d, unsigned long long a,
                                      unsigned long long b) {
    asm("fma.rn.f32x2 %0, %1, %2, %3;" : "=l"(d) : "l"(a), "l"(b), "l"(d));
}
__device__ __forceinline__ void unpack2(unsigned long long v, float& lo, float& hi) {
    asm("mov.b64 {%0, %1}, %2;" : "=f"(lo), "=f"(hi) : "l"(v));
}

// fp16 MMA m16n8k16 (legacy HMMA path -- valid on non-'a' sm_103 target)
__device__ __forceinline__ void mma16816(float* c, const uint32_t* a, const uint32_t* b) {
    asm volatile(
        "mma.sync.aligned.m16n8k16.row.col.f32.f16.f16.f32 "
        "{%0,%1,%2,%3}, {%4,%5,%6,%7}, {%8,%9}, {%0,%1,%2,%3};"
        : "+f"(c[0]), "+f"(c[1]), "+f"(c[2]), "+f"(c[3])
        : "r"(a[0]), "r"(a[1]), "r"(a[2]), "r"(a[3]), "r"(b[0]), "r"(b[1]));
}

__device__ __forceinline__ uint32_t smem_u32p(const void* p) {
    uint32_t a;
    asm("{ .reg .u64 t; cvta.to.shared.u64 t, %1; cvt.u32.u64 %0, t; }"
        : "=r"(a) : "l"(p));
    return a;
}
__device__ __forceinline__ void ldm_x4(uint32_t* r, uint32_t saddr) {
    asm volatile("ldmatrix.sync.aligned.m8n8.x4.shared.b16 {%0,%1,%2,%3}, [%4];"
                 : "=r"(r[0]), "=r"(r[1]), "=r"(r[2]), "=r"(r[3]) : "r"(saddr));
}
__device__ __forceinline__ void cpasync16(void* sdst, const void* gsrc) {
    asm volatile("cp.async.ca.shared.global [%0], [%1], 16;"
                 :: "r"(smem_u32p(sdst)), "l"(gsrc));
}
__device__ __forceinline__ void cp_commit() {
    asm volatile("cp.async.commit_group;" ::: "memory");
}
__device__ __forceinline__ void cp_wait1() {
    asm volatile("cp.async.wait_group 1;" ::: "memory");
}
__device__ __forceinline__ void cp_wait0() {
    asm volatile("cp.async.wait_group 0;" ::: "memory");
}

// pack two fp16 from floats
__device__ __forceinline__ uint32_t h2pack(float x, float y) {
    __half hx = __float2half_rn(x), hy = __float2half_rn(y);
    return ((uint32_t)__half_as_ushort(hy) << 16) | __half_as_ushort(hx);
}

// ---------------------------------------------------------------------------
// Scratch (static device globals)
// ---------------------------------------------------------------------------
__device__ __half g_xT[((size_t)kBN * kT * kHW + 64) * kCH];
// fp16 logits written by energy; softmax converts IN PLACE to attn probs.
__device__ __half g_attn_h[((size_t)kNAtt * kHW + 64) * kHW];
__device__ __half g_acc0[((size_t)kNB * kCP + 128) * kHW];
__device__ __half g_acc1[((size_t)kNB * 2 * kCP + 128) * kHW];
__device__ __half g_acc2[((size_t)kNB * 3 * kCP + 128) * kHW];

__device__ __forceinline__ __half* acc_buf(int s) {
    return s == 0 ? g_acc0 : (s == 1 ? g_acc1 : g_acc2);
}

// ---------------------------------------------------------------------------
// SMEM tile buffer (double-buffered). 128(m) x 128(n) CTA tile, K-tile = 64.
// 2 bufs * 36864 B = 73728 B/CTA -> 2 CTAs/SM.
// ---------------------------------------------------------------------------
struct Buf {
    __half Ah[128 * kLds];   // 18432 B
    __half Bh[128 * kLds];   // 18432 B
};
constexpr int kSmemDyn = 2 * sizeof(Buf);  // 73728 B

__device__ __forceinline__ void stage_tile(
    Buf& d, const __half* __restrict__ Agh, int lda,
    const __half* __restrict__ Bgh, int ldb, int k0, int tid) {
#pragma unroll
    for (int s = 0; s < 8; s++) {
        int i = s * 256 + tid;  // 0..2047; 8 float4-chunks per 64-half row
        int row = (i >> 3) & 127, c = i & 7;
        int coff = c * 8;
        if (i < 1024)
            cpasync16(&d.Ah[row * kLds + coff], Agh + (size_t)row * lda + k0 + coff);
        else
            cpasync16(&d.Bh[row * kLds + coff], Bgh + (size_t)row * ldb + k0 + coff);
    }
}

// Load the 8 B-fragments (two 64-col halves) for one 16-wide k-step.
__device__ __forceinline__ void load_bfrags(uint32_t bf[8][2], uint32_t Bh0, uint32_t kbb) {
#pragma unroll
    for (int half = 0; half < 2; half++) {
        uint32_t roff = (uint32_t)(half * 32 * kLds * 2) + kbb;
        uint32_t t[4];
        ldm_x4(t, Bh0 + roff);
        bf[half * 4 + 0][0] = t[0]; bf[half * 4 + 0][1] = t[1];
        bf[half * 4 + 1][0] = t[2]; bf[half * 4 + 1][1] = t[3];
        ldm_x4(t, Bh0 + roff + 16 * kLds * 2);
        bf[half * 4 + 2][0] = t[0]; bf[half * 4 + 2][1] = t[1];
        bf[half * 4 + 3][0] = t[2]; bf[half * 4 + 3][1] = t[3];
    }
}

// Core: C[128x128] accumulate over K (multiple of 64). 8 warps = 4(m) x 2(n),
// warp tile 32(m) x 64(n). ldmatrix fragments; B frags software-pipelined.
__device__ __forceinline__ void gemm_core(
    const __half* __restrict__ Agh, int lda,
    const __half* __restrict__ Bgh, int ldb,
    int K, float acc[2][8][4], Buf* bufs) {
    int tid = threadIdx.x;
    int wid = tid >> 5, lane = tid & 31;
    int wm = wid & 3, wn = wid >> 2;

    int j = lane >> 3, r = lane & 7;
    uint32_t aoff = (uint32_t)(((wm * 32 + ((j & 1) << 3) + r) * kLds + ((j >> 1) << 3)) * 2);
    uint32_t boff = (uint32_t)(((wn * 64 + ((j >> 1) << 3) + r) * kLds + ((j & 1) << 3)) * 2);

#pragma unroll
    for (int i = 0; i < 2; i++)
#pragma unroll
        for (int jj = 0; jj < 8; jj++)
#pragma unroll
            for (int q = 0; q < 4; q++) acc[i][jj][q] = 0.f;

    int nt = K / kKT;
    stage_tile(bufs[0], Agh, lda, Bgh, ldb, 0, tid);
    cp_commit();
    for (int kt = 0; kt < nt; kt++) {
        if (kt + 1 < nt) {
            stage_tile(bufs[(kt + 1) & 1], Agh, lda, Bgh, ldb, (kt + 1) * kKT, tid);
            cp_commit();
            cp_wait1();
        } else {
            cp_wait0();
        }
        __syncthreads();
        Buf& b = bufs[kt & 1];
        uint32_t Ah0 = smem_u32p(b.Ah) + aoff;
        uint32_t Bh0 = smem_u32p(b.Bh) + boff;

        uint32_t bbuf[2][8][2];
        load_bfrags(bbuf[0], Bh0, 0);
#pragma unroll
        for (int kb = 0; kb < 4; kb++) {
            int cur = kb & 1;
            uint32_t kbb = (uint32_t)kb * 32;  // 16 halves = 32 bytes per k-step
            uint32_t ah[2][4];
            ldm_x4(ah[0], Ah0 + kbb);
            ldm_x4(ah[1], Ah0 + 16 * kLds * 2 + kbb);
            if (kb < 3) load_bfrags(bbuf[cur ^ 1], Bh0, kbb + 32);
#pragma unroll
            for (int jj = 0; jj < 8; jj++)
#pragma unroll
                for (int mi = 0; mi < 2; mi++)
                    mma16816(acc[mi][jj], ah[mi], bbuf[cur][jj]);
        }
        __syncthreads();
    }
}

// ---------------------------------------------------------------------------
// 1) Normalize + transpose + fp16 convert: g_xT[bt*HW+pix][c]
// ---------------------------------------------------------------------------
__global__ __launch_bounds__(256) void normalize_t_kernel(const float* __restrict__ x) {
    __shared__ float sm[128][65];
    __shared__ float psum[4][64];
    __shared__ float invs[64];
    int bt = blockIdx.x, p0 = blockIdx.y * 64;
    int tid = threadIdx.x;
    int px = tid & 63, cq = tid >> 6;
    const float* xb = x + (size_t)bt * kCH * kHW + p0;
    float s = 0.f;
#pragma unroll
    for (int j = 0; j < 32; j++) {
        int c = cq * 32 + j;
        float v = xb[(size_t)c * kHW + px];
        sm[c][px] = v;
        s += v * v;
    }
    psum[cq][px] = s;
    __syncthreads();
    if (tid < 64) {
        float tot = psum[0][tid] + psum[1][tid] + psum[2][tid] + psum[3][tid];
        invs[tid] = 1.0f / fmaxf(sqrtf(tot), 1e-12f);
    }
    __syncthreads();
    float iv = invs[px];
    size_t rb = ((size_t)bt * kHW + p0 + px) * kCH + cq * 32;
#pragma unroll
    for (int j4 = 0; j4 < 8; j4++) {
        int c = cq * 32 + j4 * 4;
        uint32_t w0 = h2pack(sm[c][px] * iv, sm[c + 1][px] * iv);
        uint32_t w1 = h2pack(sm[c + 2][px] * iv, sm[c + 3][px] * iv);
        *(uint2*)(g_xT + rb + j4 * 4) = make_uint2(w0, w1);
    }
}

// ---------------------------------------------------------------------------
// 2) Value projection FUSED with cs-scatter (channels 32..127 only).
// ---------------------------------------------------------------------------
__global__ __launch_bounds__(256) void vproj_fused_kernel(const float* __restrict__ x,
                                                          const float* __restrict__ Wv,
                                                          const float* __restrict__ bv,
                                                          float* __restrict__ outp) {
    int bt = blockIdx.y;
    int p0 = blockIdx.x * 64;
    int b = bt / kT, tt = bt % kT;
    __shared__ __align__(16) float Ws[16][100];  // [c][o'] o'=0..95
    __shared__ __align__(16) float Xs[16][68];
    int tid = threadIdx.x;
    int ty = tid >> 4, tx = tid & 15;
    unsigned long long acc[3][4];
#pragma unroll
    for (int i = 0; i < 3; i++)
#pragma unroll
        for (int j = 0; j < 4; j++) acc[i][j] = 0ULL;

    const float* xb = x + (size_t)bt * kCH * kHW;
    for (int c0 = 0; c0 < kCH; c0 += 16) {
#pragma unroll
        for (int r = 0; r < 6; r++) {            // 96 o x 16 c
            int lin = r * 256 + tid;
            int o = lin >> 4, c = lin & 15;
            Ws[c][o] = Wv[(kSSTA + o) * kCH + c0 + c];
        }
#pragma unroll
        for (int r = 0; r < 4; r++) {
            int lin = r * 256 + tid;
            int c = lin >> 6, j = lin & 63;
            Xs[c][j] = xb[(size_t)(c0 + c) * kHW + p0 + j];
        }
        __syncthreads();
#pragma unroll
        for (int c = 0; c < 16; c++) {
            float4 xv = *(const float4*)&Xs[c][tx * 4];
            float w0 = Ws[c][ty * 6 + 0], w1 = Ws[c][ty * 6 + 1];
            float w2 = Ws[c][ty * 6 + 2], w3 = Ws[c][ty * 6 + 3];
            float w4 = Ws[c][ty * 6 + 4], w5 = Ws[c][ty * 6 + 5];
            unsigned long long wp[3] = {pack2(w0, w1), pack2(w2, w3), pack2(w4, w5)};
            unsigned long long xd[4] = {dup2(xv.x), dup2(xv.y), dup2(xv.z), dup2(xv.w)};
#pragma unroll
            for (int i = 0; i < 3; i++)
#pragma unroll
                for (int j = 0; j < 4; j++) ffma2(acc[i][j], wp[i], xd[j]);
        }
        __syncthreads();
    }

#pragma unroll
    for (int i = 0; i < 3; i++) {
        int cd0 = ty * 6 + 2 * i;
        float b0 = bv[kSSTA + cd0], b1 = bv[kSSTA + cd0 + 1];
        float vlo[4], vhi[4];
#pragma unroll
        for (int j = 0; j < 4; j++) {
            float lo, hi;
            unpack2(acc[i][j], lo, hi);
            vlo[j] = lo + b0;
            vhi[j] = hi + b1;
        }
        int pix = p0 + tx * 4;
        uint2 hlo = make_uint2(h2pack(vlo[0], vlo[1]), h2pack(vlo[2], vlo[3]));
        uint2 hhi = make_uint2(h2pack(vhi[0], vhi[1]), h2pack(vhi[2], vhi[3]));
#pragma unroll
        for (int s = 0; s < 4; s++) {
            int t = tt - s;
            if (t >= 0 && t < kTp) {
                int bz = b * kTp + t;
                if (s == 3) {
                    float* d = outp + ((size_t)bz * kOutC + cd0) * kHW + pix;
                    *(float4*)d = make_float4(vlo[0], vlo[1], vlo[2], vlo[3]);
                    *(float4*)(d + kHW) = make_float4(vhi[0], vhi[1], vhi[2], vhi[3]);
                } else {
                    int dc = (s + 1) * kCP;
                    __half* d = acc_buf(s) + ((size_t)bz * dc + cd0) * kHW + pix;
                    *(uint2*)d = hlo;
                    *(uint2*)(d + kHW) = hhi;
                }
            }
        }
    }
}

// ---------------------------------------------------------------------------
// 3) Positional-encoding FUSED scatter: cs channels 96..113 for all stages.
// ---------------------------------------------------------------------------
__global__ __launch_bounds__(256) void pe_fill_fused_kernel(float* __restrict__ outp) {
    int gid = blockIdx.x * 256 + threadIdx.x;
    const int total = kBN * kT * 18 * kHW;
    if (gid >= total) return;
    int bt  = gid / (18 * kHW);
    int rem = gid % (18 * kHW);
    int c = rem / kHW, pix = rem % kHW;
    int yy = pix / kW, xx = pix % kW;
    float yc = -1.0f + 2.0f * (float)yy / (float)(kH - 1);
    float xc = -1.0f + 2.0f * (float)xx / (float)(kW - 1);
    float val;
    if (c == 0) val = yc;
    else if (c == 1) val = xc;
    else {
        int i = (c - 2) >> 2;
        int k = (c - 2) & 3;
        float coord = (k & 1) ? xc : yc;
        float f = (float)(1 << i) * 3.14159265358979323846f * coord;
        val = (k < 2) ? sinf(f) : cosf(f);
    }
    int b = bt / kT, tt = bt % kT;
    int cd = 96 + c;
    __half hv = __float2half_rn(val);
#pragma unroll
    for (int s = 0; s < 4; s++) {
        int t = tt - s;
        if (t >= 0 && t < kTp) {
            int bz = b * kTp + t;
            if (s == 3)
                outp[((size_t)bz * kOutC + cd) * kHW + pix] = val;
            else
                acc_buf(s)[((size_t)bz * (s + 1) * kCP + cd) * kHW + pix] = hv;
        }
    }
}

// ---------------------------------------------------------------------------
// 4) Energy GEMM: logits[g,n,m] = scale * sum_c qT[n,c]*kT[m,c]; out fp16.
//    grid = (5 m-tiles(128), 5 n-tiles(128), 176 g)
// ---------------------------------------------------------------------------
__global__ __launch_bounds__(256, 2) void energy_mma_kernel() {
    extern __shared__ __align__(16) char smem[];
    int g = blockIdx.z;
    int b = g / kTm1, t = g % kTm1;
    int m0 = blockIdx.y * 128, n0 = blockIdx.x * 128;
    size_t abase = ((size_t)(b * kT + t + 1) * kHW + m0) * kCH;
    size_t bbase = ((size_t)(b * kT + t) * kHW + n0) * kCH;
    float acc[2][8][4];
    gemm_core(g_xT + abase, kCH, g_xT + bbase, kCH, kCH, acc, (Buf*)smem);

    int tid = threadIdx.x;
    int wid = tid >> 5, lane = tid & 31;
    int quad = lane >> 2, tq = lane & 3;
    int wm = wid & 3, wn = wid >> 2;
    int mvalid = kHW - m0;
    __half* C = g_attn_h + (size_t)g * kHW * kHW + (size_t)m0 * kHW;
#pragma unroll
    for (int mi = 0; mi < 2; mi++)
#pragma unroll
        for (int rh = 0; rh < 2; rh++) {
            int rrow = wm * 32 + mi * 16 + quad + rh * 8;
            if (rrow < mvalid) {
#pragma unroll
                for (int ni = 0; ni < 8; ni++) {
                    int ncol = n0 + wn * 64 + ni * 8 + tq * 2;
                    if (ncol < kHW) {
                        uint32_t hw = h2pack(acc[mi][ni][rh * 2] * kScale,
                                             acc[mi][ni][rh * 2 + 1] * kScale);
                        *(uint32_t*)(C + (size_t)rrow * kHW + ncol) = hw;
                    }
                }
            }
        }
}

// ---------------------------------------------------------------------------
// 5) Softmax: one warp per row, 8 rows per block, pure shuffle reductions,
//    IN PLACE on fp16 logits -> fp16 probabilities.
// ---------------------------------------------------------------------------
__global__ __launch_bounds__(256) void softmax_kernel() {
    int wid = threadIdx.x >> 5, lane = threadIdx.x & 31;
    size_t row = (size_t)blockIdx.x * 8 + wid;
    __half2* p = (__half2*)(g_attn_h + row * kHW);   // 288 half2 per row
    __half2 v[9];
#pragma unroll
    for (int k = 0; k < 9; k++) v[k] = p[lane + 32 * k];
    float m = -3.0e38f;
#pragma unroll
    for (int k = 0; k < 9; k++) {
        float2 f = __half22float2(v[k]);
        m = fmaxf(m, fmaxf(f.x, f.y));
    }
#pragma unroll
    for (int off = 16; off > 0; off >>= 1)
        m = fmaxf(m, __shfl_xor_sync(0xffffffffu, m, off));
    float e[18];
    float s = 0.f;
#pragma unroll
    for (int k = 0; k < 9; k++) {
        float2 f = __half22float2(v[k]);
        e[2 * k] = expf(f.x - m);
        e[2 * k + 1] = expf(f.y - m);
        s += e[2 * k] + e[2 * k + 1];
    }
#pragma unroll
    for (int off = 16; off > 0; off >>= 1)
        s += __shfl_xor_sync(0xffffffffu, s, off);
    float inv = 1.0f / s;
#pragma unroll
    for (int k = 0; k < 9; k++)
        p[lane + 32 * k] = __floats2half2_rn(e[2 * k] * inv, e[2 * k + 1] * inv);
}

// ---------------------------------------------------------------------------
// 6) Propagation GEMM: dst[bz,114+c,n] = sum_m A[bz,c,m]*attn[b,t0+t,n,m]
//    grid = (5 n-tiles(128), Mtiles(128), 144 bz).
// ---------------------------------------------------------------------------
__global__ __launch_bounds__(256, 2) void prop_mma_kernel(int dstSel, float* outp,
                                                          int srcSel, int dstC, int Cin,
                                                          int t0) {
    extern __shared__ __align__(16) char smem[];
    int bz = blockIdx.z;
    int b = bz / kTp, t = bz % kTp;
    int c0 = blockIdx.y * 128, n0 = blockIdx.x * 128;
    size_t abase = ((size_t)bz * Cin + c0) * kHW;
    size_t bbase = ((size_t)b * kTm1 + t0 + t) * kHW * kHW + (size_t)n0 * kHW;
    float acc[2][8][4];
    gemm_core(acc_buf(srcSel) + abase, kHW, g_attn_h + bbase, kHW, kHW, acc, (Buf*)smem);

    int tid = threadIdx.x;
    int wid = tid >> 5, lane = tid & 31;
    int quad = lane >> 2, tq = lane & 3;
    int wm = wid & 3, wn = wid >> 2;
#pragma unroll
    for (int mi = 0; mi < 2; mi++)
#pragma unroll
        for (int rh = 0; rh < 2; rh++) {
            int rloc = wm * 32 + mi * 16 + quad + rh * 8;
            int cg = c0 + rloc;
            if (cg < Cin) {
                size_t rbase = ((size_t)bz * dstC + kCP + cg) * kHW;
#pragma unroll
                for (int ni = 0; ni < 8; ni++) {
                    int ncol = n0 + wn * 64 + ni * 8 + tq * 2;
                    if (ncol < kHW) {
                        if (dstSel == 3) {
                            float2 v = make_float2(acc[mi][ni][rh * 2],
                                                   acc[mi][ni][rh * 2 + 1]);
                            *(float2*)(outp + rbase + ncol) = v;
                        } else {
                            uint32_t hw = h2pack(acc[mi][ni][rh * 2],
                                                 acc[mi][ni][rh * 2 + 1]);
                            *(uint32_t*)(acc_buf(dstSel) + rbase + ncol) = hw;
                        }
                    }
                }
            }
        }
}

// ---------------------------------------------------------------------------
extern "C" void kernel_launch(void* const* d_in, const int* in_sizes, int n_in,
                              void* d_out, int out_size) {
    const float* x  = (const float*)d_in[0];
    const float* Wv = (const float*)d_in[1];
    const float* bv = (const float*)d_in[2];
    float* out = (float*)d_out;

    static bool attrs_set = false;
    if (!attrs_set) {
        cudaFuncSetAttribute(energy_mma_kernel,
                             cudaFuncAttributeMaxDynamicSharedMemorySize, kSmemDyn);
        cudaFuncSetAttribute(prop_mma_kernel,
                             cudaFuncAttributeMaxDynamicSharedMemorySize, kSmemDyn);
        attrs_set = true;
    }

    normalize_t_kernel<<<dim3(kBN * kT, kHW / 64), 256>>>(x);
    vproj_fused_kernel<<<dim3(kHW / 64, kBN * kT), 256>>>(x, Wv, bv, out);
    pe_fill_fused_kernel<<<(kBN * kT * 18 * kHW + 255) / 256, 256>>>(out);
    energy_mma_kernel<<<dim3(5, 5, kNAtt), 256, kSmemDyn>>>();
    softmax_kernel<<<kNAtt * kHW / 8, 256>>>();
    prop_mma_kernel<<<dim3(5, 1, kNB), 256, kSmemDyn>>>(1, out, 0, 2 * kCP, kCP, 0);
    prop_mma_kernel<<<dim3(5, 2, kNB), 256, kSmemDyn>>>(2, out, 1, 3 * kCP, 2 * kCP, 1);
    prop_mma_kernel<<<dim3(5, 3, kNB), 256, kSmemDyn>>>(3, out, 2, 4 * kCP, 3 * kCP, 2);
}